// round 10
// baseline (speedup 1.0000x reference)
#include <cuda_runtime.h>
#include <math.h>

// Problem constants
#define BB 32
#define LL 1024
#define EMB 128
#define HH 384
#define NLAYER 4
#define NVOCAB 100
#define G4 (4*HH)          // 1536
#define MM (BB*LL)         // 32768
#define CTXIN 300
#define HB (HH*BB)         // 12288
#define NCTA 96            // persistent LSTM CTAs
#define HP 388             // smem h row pitch (floats), %32==4 -> conflict-free LDS.128

// ---------------- static scratch (no allocations allowed) ----------------
__device__ float g_x0[MM * 2 * EMB];            // layer-0 input [M,256]
__device__ float g_seqA[MM * HH];
__device__ float g_seqB[MM * HH];
__device__ float g_pre[(size_t)MM * G4];        // input projection [m=b*L+t][1536]
__device__ float g_preT[(size_t)MM * G4];       // transposed [t][row][b]
__device__ float g_keys[MM * HH];               // keys, later reused as ctx_vec
__device__ float g_scores[(size_t)BB * LL * LL];// attention scores / attn (in place)
__device__ float g_cat[MM * 2 * HH];            // [out | ctx]
__device__ float g_comb[MM * HH];
__device__ float g_hT[2 * HB];                  // double-buffered h, [b][k] layout
__device__ unsigned g_barCount;                 // grid barrier arrival counter

// ---------------- f32x2 packed-FMA helpers (PTX-only on sm_103a) ---------
__device__ __forceinline__ void fma2(unsigned long long& acc,
                                     unsigned long long a, unsigned long long b) {
    asm("fma.rn.f32x2 %0, %1, %2, %0;" : "+l"(acc) : "l"(a), "l"(b));
}
__device__ __forceinline__ unsigned long long pack2(float x, float y) {
    unsigned long long r;
    asm("mov.b64 %0, {%1, %2};" : "=l"(r) : "f"(x), "f"(y));
    return r;
}
__device__ __forceinline__ void unpack2(unsigned long long v, float& x, float& y) {
    asm("mov.b64 {%0, %1}, %2;" : "=f"(x), "=f"(y) : "l"(v));
}

// release arrival + acquire poll: no gpu-scope fence -> no CCTL.IVALL L1 flush
__device__ __forceinline__ void bar_arrive_release(unsigned* p) {
    asm volatile("red.release.gpu.add.u32 [%0], %1;" :: "l"(p), "r"(1u) : "memory");
}
__device__ __forceinline__ unsigned ld_acquire(unsigned* p) {
    unsigned v;
    asm volatile("ld.acquire.gpu.u32 %0, [%1];" : "=r"(v) : "l"(p) : "memory");
    return v;
}

// ---------------- tf32 helpers ----------------
__device__ __forceinline__ unsigned f2tf(float x) {
    unsigned r;
    asm("cvt.rna.tf32.f32 %0, %1;" : "=r"(r) : "f"(x));
    return r;
}

__device__ __forceinline__ void mma8(float* c, const unsigned* a, const unsigned* b) {
    asm volatile(
        "mma.sync.aligned.m16n8k8.row.col.f32.tf32.tf32.f32 "
        "{%0,%1,%2,%3}, {%4,%5,%6,%7}, {%8,%9}, {%0,%1,%2,%3};"
        : "+f"(c[0]), "+f"(c[1]), "+f"(c[2]), "+f"(c[3])
        : "r"(a[0]), "r"(a[1]), "r"(a[2]), "r"(a[3]), "r"(b[0]), "r"(b[1]));
}

// ---------------- tensor-core GEMM (3xTF32, ~fp32 accuracy) ----------------
// C = act(scale * (A @ OP) + b1 + b2)
//   trans=1: OP = W^T, W[N,K] row-major.  trans=0: OP = B, B[K,N] row-major.
#define SP 132
__global__ __launch_bounds__(256)
void gemm_tc(const float* __restrict__ A, int lda,
             const float* __restrict__ W, int ldw,
             const float* __restrict__ b1, const float* __restrict__ b2,
             float* __restrict__ C, int ldc,
             int M, int N, int K,
             float scale, int act, int causal, int causalK, int trans,
             size_t sA, size_t sW, size_t sC)
{
    int m0 = blockIdx.y * 128;
    int n0 = blockIdx.x * 128;
    if (causal && n0 > m0 + 127) return;
    A += (size_t)blockIdx.z * sA;
    W += (size_t)blockIdx.z * sW;
    C += (size_t)blockIdx.z * sC;
    int Klim = causalK ? min(K, m0 + 128) : K;

    __shared__ float As_hi[16 * SP], As_lo[16 * SP];
    __shared__ float Bs_hi[16 * SP], Bs_lo[16 * SP];

    const int tid = threadIdx.x;
    const int lr = tid >> 1, lq = tid & 1;
    const int kr = tid >> 4, nc = (tid & 15) * 8;
    const int lane = tid & 31;
    const int g = lane >> 2, tg = lane & 3;
    const int wid = tid >> 5;
    const int mBase = (wid & 3) * 32;
    const int nBase = (wid >> 2) * 64;

    float acc[2][8][4];
#pragma unroll
    for (int mt = 0; mt < 2; mt++)
#pragma unroll
        for (int nt = 0; nt < 8; nt++)
#pragma unroll
            for (int i = 0; i < 4; i++) acc[mt][nt][i] = 0.f;

    float4 a4[2], b4[2];

#define LOAD_TILE(K0)                                                          \
    {                                                                          \
        int k0_ = (K0);                                                        \
        const float* ap = A + (size_t)(m0 + lr) * lda;                         \
        _Pragma("unroll")                                                      \
        for (int j = 0; j < 2; j++) {                                          \
            int kb = k0_ + lq * 8 + j * 4;                                     \
            float4 v = make_float4(0.f, 0.f, 0.f, 0.f);                        \
            if (kb + 3 < Klim) v = *(const float4*)(ap + kb);                  \
            else {                                                             \
                if (kb + 0 < Klim) v.x = ap[kb + 0];                           \
                if (kb + 1 < Klim) v.y = ap[kb + 1];                           \
                if (kb + 2 < Klim) v.z = ap[kb + 2];                           \
            }                                                                  \
            a4[j] = v;                                                         \
        }                                                                      \
        if (trans) {                                                           \
            int wr = n0 + lr;                                                  \
            const float* wp = W + (size_t)wr * ldw;                            \
            _Pragma("unroll")                                                  \
            for (int j = 0; j < 2; j++) {                                      \
                int kb = k0_ + lq * 8 + j * 4;                                 \
                float4 v = make_float4(0.f, 0.f, 0.f, 0.f);                    \
                if (wr < N) {                                                  \
                    if (kb + 3 < Klim) v = *(const float4*)(wp + kb);          \
                    else {                                                     \
                        if (kb + 0 < Klim) v.x = wp[kb + 0];                   \
                        if (kb + 1 < Klim) v.y = wp[kb + 1];                   \
                        if (kb + 2 < Klim) v.z = wp[kb + 2];                   \
                    }                                                          \
                }                                                              \
                b4[j] = v;                                                     \
            }                                                                  \
        } else {                                                               \
            int kk = k0_ + kr;                                                 \
            _Pragma("unroll")                                                  \
            for (int j = 0; j < 2; j++) {                                      \
                float4 v = make_float4(0.f, 0.f, 0.f, 0.f);                    \
                if (kk < Klim)                                                 \
                    v = *(const float4*)(W + (size_t)kk * ldw + n0 + nc + j * 4);\
                b4[j] = v;                                                     \
            }                                                                  \
        }                                                                      \
    }

    LOAD_TILE(0);

    for (int k0 = 0; k0 < Klim; k0 += 16) {
#pragma unroll
        for (int j = 0; j < 2; j++) {
            const float* pv = &a4[j].x;
            int kb = lq * 8 + j * 4;
#pragma unroll
            for (int i = 0; i < 4; i++) {
                float a = pv[i];
                float hf = __uint_as_float(f2tf(a));
                As_hi[(kb + i) * SP + lr] = hf;
                As_lo[(kb + i) * SP + lr] = __uint_as_float(f2tf(a - hf));
            }
        }
        if (trans) {
#pragma unroll
            for (int j = 0; j < 2; j++) {
                const float* pv = &b4[j].x;
                int kb = lq * 8 + j * 4;
#pragma unroll
                for (int i = 0; i < 4; i++) {
                    float a = pv[i];
                    float hf = __uint_as_float(f2tf(a));
                    Bs_hi[(kb + i) * SP + lr] = hf;
                    Bs_lo[(kb + i) * SP + lr] = __uint_as_float(f2tf(a - hf));
                }
            }
        } else {
#pragma unroll
            for (int j = 0; j < 2; j++) {
                const float* pv = &b4[j].x;
#pragma unroll
                for (int i = 0; i < 4; i++) {
                    float a = pv[i];
                    float hf = __uint_as_float(f2tf(a));
                    Bs_hi[kr * SP + nc + j * 4 + i] = hf;
                    Bs_lo[kr * SP + nc + j * 4 + i] = __uint_as_float(f2tf(a - hf));
                }
            }
        }
        __syncthreads();

        if (k0 + 16 < Klim) LOAD_TILE(k0 + 16);

#pragma unroll
        for (int kt = 0; kt < 2; kt++) {
            int kr0 = kt * 8 + tg, kr1 = kt * 8 + tg + 4;
            unsigned ah[2][4], al[2][4];
#pragma unroll
            for (int mt = 0; mt < 2; mt++) {
                int m = mBase + mt * 16 + g;
                ah[mt][0] = __float_as_uint(As_hi[kr0 * SP + m]);
                ah[mt][1] = __float_as_uint(As_hi[kr0 * SP + m + 8]);
                ah[mt][2] = __float_as_uint(As_hi[kr1 * SP + m]);
                ah[mt][3] = __float_as_uint(As_hi[kr1 * SP + m + 8]);
                al[mt][0] = __float_as_uint(As_lo[kr0 * SP + m]);
                al[mt][1] = __float_as_uint(As_lo[kr0 * SP + m + 8]);
                al[mt][2] = __float_as_uint(As_lo[kr1 * SP + m]);
                al[mt][3] = __float_as_uint(As_lo[kr1 * SP + m + 8]);
            }
#pragma unroll
            for (int nt = 0; nt < 8; nt++) {
                int n = nBase + nt * 8 + g;
                unsigned bh[2], bl[2];
                bh[0] = __float_as_uint(Bs_hi[kr0 * SP + n]);
                bh[1] = __float_as_uint(Bs_hi[kr1 * SP + n]);
                bl[0] = __float_as_uint(Bs_lo[kr0 * SP + n]);
                bl[1] = __float_as_uint(Bs_lo[kr1 * SP + n]);
#pragma unroll
                for (int mt = 0; mt < 2; mt++) {
                    mma8(acc[mt][nt], ah[mt], bh);
                    mma8(acc[mt][nt], ah[mt], bl);
                    mma8(acc[mt][nt], al[mt], bh);
                }
            }
        }
        __syncthreads();
    }

#pragma unroll
    for (int mt = 0; mt < 2; mt++) {
        int row0 = m0 + mBase + mt * 16 + g;
        int row1 = row0 + 8;
#pragma unroll
        for (int nt = 0; nt < 8; nt++) {
            int col = n0 + nBase + nt * 8 + 2 * tg;
            float bias = 0.f;
            float bias1 = 0.f;
            if (col < N) {
                if (b1) bias += b1[col];
                if (b2) bias += b2[col];
            }
            if (col + 1 < N) {
                if (b1) bias1 += b1[col + 1];
                if (b2) bias1 += b2[col + 1];
            }
            float v0 = acc[mt][nt][0] * scale + bias;
            float v1 = acc[mt][nt][1] * scale + bias1;
            float v2 = acc[mt][nt][2] * scale + bias;
            float v3 = acc[mt][nt][3] * scale + bias1;
            if (act) { v0 = tanhf(v0); v1 = tanhf(v1); v2 = tanhf(v2); v3 = tanhf(v3); }
            if (col + 1 < N) {
                *(float2*)(C + (size_t)row0 * ldc + col) = make_float2(v0, v1);
                *(float2*)(C + (size_t)row1 * ldc + col) = make_float2(v2, v3);
            } else if (col < N) {
                C[(size_t)row0 * ldc + col] = v0;
                C[(size_t)row1 * ldc + col] = v2;
            }
        }
    }
}

// ---------------- embedding gather ----------------
__global__ void embed_kernel(const int* __restrict__ x, const float* __restrict__ emb,
                             float* __restrict__ X0)
{
    int i = blockIdx.x * 256 + threadIdx.x;
    if (i >= MM * EMB) return;
    int m = i >> 7, e = i & 127;
    X0[(size_t)m * 256 + e] = emb[(size_t)x[m] * EMB + e];
}

// ---------------- pre transpose: [b*L+t][row] -> [t][row][b] ------------
__global__ __launch_bounds__(1024)
void transpose_pre(const float* __restrict__ in, float* __restrict__ out)
{
    __shared__ float tile[32][33];
    int t = blockIdx.x;
    int r0 = blockIdx.y * 32;
    int x = threadIdx.x, y = threadIdx.y;
    tile[y][x] = in[((size_t)y * LL + t) * G4 + r0 + x];
    __syncthreads();
    out[((size_t)t * G4 + r0 + y) * BB + x] = tile[x][y];
}

// ---------------- persistent LSTM layer ----------------
// 96 CTAs x 128 threads (4 hidden dims x 32 batch per CTA), 1 warp/SMSP.
// Release/acquire grid barrier (no gpu-scope fence -> no per-step L1 flush).
// h state [b][k] in global; staged into pitch-388 smem for LDS.128 reads.
__global__ __launch_bounds__(128, 1)
void lstm_layer(const float* __restrict__ preT,  // [t][row][b]
                const float* __restrict__ Whh,   // [1536,384]
                const float* __restrict__ h0,    // [B,H]
                const float* __restrict__ c0,    // [B,H]
                float* __restrict__ Y,           // [B,L,H]
                float* __restrict__ hT,          // [2][B][H]
                float* __restrict__ outh,        // [B,H] or null
                float* __restrict__ outc,
                int writeState)
{
    extern __shared__ float sm[];
    float* hs = sm;                         // 32 rows x pitch HP  (49664 B)
    float2* smA = (float2*)(sm + BB * HP);  // 4*384 float2: {Wi,Wf} pairs
    float2* smB = smA + 4 * HH;             // 4*384 float2: {Wg,Wo} pairs

    const int tid = threadIdx.x;
    const int b = tid & 31;
    const int jl = tid >> 5;
    const int jg = blockIdx.x * 4 + jl;

    // stage interleaved weights into smem (once)
    {
        const float* w0 = Whh + (size_t)jg * HH;
        const float* w1 = w0 + (size_t)HH * HH;
        const float* w2 = w1 + (size_t)HH * HH;
        const float* w3 = w2 + (size_t)HH * HH;
        for (int k = b; k < HH; k += 32) {
            smA[jl * HH + k] = make_float2(w0[k], w1[k]);
            smB[jl * HH + k] = make_float2(w2[k], w3[k]);
        }
    }

    float h = h0[b * HH + jg];
    float c = c0[b * HH + jg];
    hT[b * HH + jg] = h;       // buffer 0, [b][k] layout

    const float2* wa = smA + jl * HH;
    const float2* wb = smB + jl * HH;
    float* hrow = hs + b * HP;
    const int yb = blockIdx.x / 3;                 // Y-writer slice: batch
    const int ykc = (blockIdx.x % 3) * 128 + tid;  // Y-writer slice: hidden dim

    for (int t = 0; t < LL; t++) {
        // prefetch pre(t) into registers (L2 latency hides under barrier)
        size_t base = ((size_t)t * G4) * BB + b;
        float p0 = __ldcg(&preT[base + (size_t)jg * BB]);
        float p1 = __ldcg(&preT[base + (size_t)(HH + jg) * BB]);
        float p2 = __ldcg(&preT[base + (size_t)(2 * HH + jg) * BB]);
        float p3 = __ldcg(&preT[base + (size_t)(3 * HH + jg) * BB]);

        // ---- grid barrier #(t+1): release arrive + acquire poll ----
        __syncthreads();                 // all h stores of prev step done (CTA)
        if (tid == 0) {
            bar_arrive_release(&g_barCount);
            unsigned tgt = (unsigned)NCTA * (unsigned)(t + 1);
            while (ld_acquire(&g_barCount) < tgt) {}
        }
        __syncthreads();

        // ---- stage h(t) [b][k] global -> [b][k]-pitched smem ----
        // float4 index idx covers floats 4*idx..4*idx+3: b = idx/96, k4 = idx%96
        {
            const float4* src = (const float4*)(hT + (t & 1) * HB);
#pragma unroll
            for (int i = 0; i < 24; i++) {
                int idx = tid + i * 128;
                int bb = idx / 96;
                int kk = idx - bb * 96;
                *(float4*)(hs + bb * HP + kk * 4) = __ldcv(src + idx);
            }
        }
        __syncthreads();

        // coalesced Y[t-1] write from staged full-h (disjoint CTA slices)
        if (t > 0)
            Y[((size_t)yb * LL + (t - 1)) * HH + ykc] = hs[yb * HP + ykc];

        // ---- gates: packed {i,f} and {g,o} accumulation ----
        unsigned long long acc01 = pack2(p0, p1);
        unsigned long long acc23 = pack2(p2, p3);
#pragma unroll 8
        for (int k = 0; k < HH; k += 4) {
            ulonglong2 A0 = *(const ulonglong2*)(wa + k);      // {k, k+1}
            ulonglong2 A1 = *(const ulonglong2*)(wa + k + 2);  // {k+2, k+3}
            ulonglong2 B0 = *(const ulonglong2*)(wb + k);
            ulonglong2 B1 = *(const ulonglong2*)(wb + k + 2);
            float4 hv = *(const float4*)(hrow + k);            // LDS.128
            unsigned long long hh0 = pack2(hv.x, hv.x);
            unsigned long long hh1 = pack2(hv.y, hv.y);
            unsigned long long hh2 = pack2(hv.z, hv.z);
            unsigned long long hh3 = pack2(hv.w, hv.w);
            fma2(acc01, A0.x, hh0); fma2(acc23, B0.x, hh0);
            fma2(acc01, A0.y, hh1); fma2(acc23, B0.y, hh1);
            fma2(acc01, A1.x, hh2); fma2(acc23, B1.x, hh2);
            fma2(acc01, A1.y, hh3); fma2(acc23, B1.y, hh3);
        }
        float g0, g1, g2, g3;
        unpack2(acc01, g0, g1);
        unpack2(acc23, g2, g3);

        float ig = 1.f / (1.f + expf(-g0));
        float fg = 1.f / (1.f + expf(-g1));
        float gg = tanhf(g2);
        float og = 1.f / (1.f + expf(-g3));
        c = fg * c + ig * gg;
        h = og * tanhf(c);

        hT[((t + 1) & 1) * HB + b * HH + jg] = h;
    }

    // tail: Y[L-1]
    Y[((size_t)b * LL + (LL - 1)) * HH + jg] = h;

    if (writeState) {
        outh[b * HH + jg] = h;
        outc[b * HH + jg] = c;
    }
}

// ---------------- causal softmax (in place, zero-fills masked region) ----
__global__ __launch_bounds__(256)
void softmax_causal(float* __restrict__ S)
{
    int bq = blockIdx.x;
    int b = bq >> 10, q = bq & 1023;
    float* row = S + ((size_t)b * LL + q) * LL;
    int len = q + 1;
    int tid = threadIdx.x;
    __shared__ float red[256];

    float mx = -1e30f;
    for (int k = tid; k < len; k += 256) mx = fmaxf(mx, row[k]);
    red[tid] = mx; __syncthreads();
    for (int s = 128; s > 0; s >>= 1) {
        if (tid < s) red[tid] = fmaxf(red[tid], red[tid + s]);
        __syncthreads();
    }
    mx = red[0]; __syncthreads();

    float sum = 0.f;
    for (int k = tid; k < len; k += 256) sum += expf(row[k] - mx);
    red[tid] = sum; __syncthreads();
    for (int s = 128; s > 0; s >>= 1) {
        if (tid < s) red[tid] += red[tid + s];
        __syncthreads();
    }
    sum = red[0]; __syncthreads();

    float inv = 1.f / sum;
    for (int k = tid; k < LL; k += 256)
        row[k] = (k < len) ? expf(row[k] - mx) * inv : 0.f;
}

// ---------------- concat [out | ctx] ----------------
__global__ void concat_kernel(const float* __restrict__ Yout, const float* __restrict__ ctx,
                              float* __restrict__ cat)
{
    int i = blockIdx.x * 256 + threadIdx.x;
    if (i >= MM * 2 * HH) return;
    int m = i / (2 * HH), j = i % (2 * HH);
    cat[i] = (j < HH) ? Yout[(size_t)m * HH + j] : ctx[(size_t)m * HH + j - HH];
}

// ---------------- host ----------------
extern "C" void kernel_launch(void* const* d_in, const int* in_sizes, int n_in,
                              void* d_out, int out_size)
{
    const int*   x       = (const int*)d_in[0];
    const float* context = (const float*)d_in[1];
    const float* h_in    = (const float*)d_in[2];
    const float* c_in    = (const float*)d_in[3];
    const float* emb     = (const float*)d_in[4];
    const float* ctx_W   = (const float*)d_in[5];
    const float* ctx_b   = (const float*)d_in[6];
    const float* Wih0    = (const float*)d_in[7];
    const float* WihR    = (const float*)d_in[8];
    const float* Whh     = (const float*)d_in[9];
    const float* bih     = (const float*)d_in[10];
    const float* bhh     = (const float*)d_in[11];
    const float* Wa      = (const float*)d_in[12];
    const float* comb_W  = (const float*)d_in[13];
    const float* comb_b  = (const float*)d_in[14];
    const float* fc_W    = (const float*)d_in[15];
    const float* fc_b    = (const float*)d_in[16];
    float* out = (float*)d_out;

    float *x0, *seqA, *seqB, *pre, *preT, *keys, *scores, *cat, *comb, *hT;
    unsigned* barCount;
    cudaGetSymbolAddress((void**)&x0,       g_x0);
    cudaGetSymbolAddress((void**)&seqA,     g_seqA);
    cudaGetSymbolAddress((void**)&seqB,     g_seqB);
    cudaGetSymbolAddress((void**)&pre,      g_pre);
    cudaGetSymbolAddress((void**)&preT,     g_preT);
    cudaGetSymbolAddress((void**)&keys,     g_keys);
    cudaGetSymbolAddress((void**)&scores,   g_scores);
    cudaGetSymbolAddress((void**)&cat,      g_cat);
    cudaGetSymbolAddress((void**)&comb,     g_comb);
    cudaGetSymbolAddress((void**)&hT,       g_hT);
    cudaGetSymbolAddress((void**)&barCount, g_barCount);

    const int lstmSmem = BB * HP * 4 + 2 * 4 * HH * 8;   // 49664 + 24576 = 74240
    cudaFuncSetAttribute(lstm_layer, cudaFuncAttributeMaxDynamicSharedMemorySize, lstmSmem);

    const int logitsN = MM * NVOCAB;             // 3,276,800
    const bool wantState = (out_size >= logitsN + 2 * NLAYER * BB * HH);

    // 1) embedding + context projection -> x0 [M,256]
    embed_kernel<<<(MM * EMB + 255) / 256, 256>>>(x, emb, x0);
    gemm_tc<<<dim3(1, 256, 1), 256>>>(context, CTXIN, ctx_W, CTXIN, ctx_b, nullptr,
                                      x0 + EMB, 2 * EMB, MM, EMB, CTXIN,
                                      1.f, 0, 0, 0, 1, 0, 0, 0);

    // 2) LSTM layers
    for (int l = 0; l < NLAYER; l++) {
        const float* X   = (l == 0) ? x0 : ((l == 1) ? seqA : ((l == 2) ? seqB : seqA));
        int          Kl  = (l == 0) ? 2 * EMB : HH;
        float*       Y   = (l % 2 == 0) ? seqA : seqB;
        const float* Wih = (l == 0) ? Wih0 : (WihR + (size_t)(l - 1) * G4 * HH);

        gemm_tc<<<dim3(G4 / 128, MM / 128, 1), 256>>>(X, Kl, Wih, Kl,
                                                      bih + l * G4, bhh + l * G4,
                                                      pre, G4, MM, G4, Kl,
                                                      1.f, 0, 0, 0, 1, 0, 0, 0);
        transpose_pre<<<dim3(LL, G4 / 32), dim3(32, 32)>>>(pre, preT);

        cudaMemsetAsync(barCount, 0, sizeof(unsigned));
        const float* Whh_l = Whh + (size_t)l * G4 * HH;
        float* outh = wantState ? (out + logitsN + l * BB * HH) : nullptr;
        float* outc = wantState ? (out + logitsN + NLAYER * BB * HH + l * BB * HH) : nullptr;
        lstm_layer<<<NCTA, 128, lstmSmem>>>(preT, Whh_l,
                                            h_in + l * BB * HH, c_in + l * BB * HH,
                                            Y, hT, outh, outc, wantState ? 1 : 0);
    }
    float* Y3 = seqB;  // layer-3 output

    // 3) attention
    gemm_tc<<<dim3(HH / 128, MM / 128, 1), 256>>>(Y3, HH, Wa, HH, nullptr, nullptr,
                                                  keys, HH, MM, HH, HH,
                                                  1.f, 0, 0, 0, 1, 0, 0, 0);
    float invs = 1.f / sqrtf((float)HH);
    gemm_tc<<<dim3(8, 8, 32), 256>>>(Y3, HH, keys, HH, nullptr, nullptr,
                                     scores, LL, LL, LL, HH,
                                     invs, 0, 1, 0, 1,
                                     (size_t)LL * HH, (size_t)LL * HH, (size_t)LL * LL);
    softmax_causal<<<BB * LL, 256>>>(scores);
    gemm_tc<<<dim3(HH / 128, 8, 32), 256>>>(scores, LL, Y3, HH, nullptr, nullptr,
                                            keys, HH, LL, HH, LL,
                                            1.f, 0, 0, 1, 0,
                                            (size_t)LL * LL, (size_t)LL * HH, (size_t)LL * HH);

    // 4) combine + output head
    concat_kernel<<<(MM * 2 * HH + 255) / 256, 256>>>(Y3, keys, cat);
    gemm_tc<<<dim3(HH / 128, MM / 128, 1), 256>>>(cat, 2 * HH, comb_W, 2 * HH,
                                                  comb_b, nullptr, comb, HH,
                                                  MM, HH, 2 * HH,
                                                  1.f, 1, 0, 0, 1, 0, 0, 0);
    gemm_tc<<<dim3(1, MM / 128, 1), 256>>>(comb, HH, fc_W, HH, fc_b, nullptr,
                                           out, NVOCAB, MM, NVOCAB, HH,
                                           1.f, 0, 0, 0, 1, 0, 0, 0);
}

// round 11
// speedup vs baseline: 1.4745x; 1.4745x over previous
#include <cuda_runtime.h>
#include <math.h>

#define BB 32
#define LL 1024
#define EMB 128
#define HH 384
#define NLAYER 4
#define NVOCAB 100
#define G4 (4*HH)
#define MM (BB*LL)
#define CTXIN 300
#define HB (HH*BB)
#define NWCTA 128          // wavefront CTAs (32 per layer)

// ---------------- static scratch ----------------
__device__ float g_x0[MM * 2 * EMB];
__device__ float g_seqB[MM * HH];               // Y3 [B,L,H]
__device__ float g_pre[(size_t)MM * G4];
__device__ float g_preT[(size_t)MM * G4];       // [t][row][b]
__device__ float g_keys[MM * HH];
__device__ float g_scores[(size_t)BB * LL * LL];
__device__ float g_cat[MM * 2 * HH];
__device__ float g_comb[MM * HH];
__device__ float g_hS[2 * NLAYER * HB];         // wavefront state [parity][l][b][k]
__device__ unsigned g_barCount;

// ---------------- f32x2 packed-FMA helpers ----------------
__device__ __forceinline__ void fma2(unsigned long long& acc,
                                     unsigned long long a, unsigned long long b) {
    asm("fma.rn.f32x2 %0, %1, %2, %0;" : "+l"(acc) : "l"(a), "l"(b));
}
__device__ __forceinline__ unsigned long long pack2(float x, float y) {
    unsigned long long r;
    asm("mov.b64 %0, {%1, %2};" : "=l"(r) : "f"(x), "f"(y));
    return r;
}
__device__ __forceinline__ void unpack2(unsigned long long v, float& x, float& y) {
    asm("mov.b64 {%0, %1}, %2;" : "=f"(x), "=f"(y) : "l"(v));
}
__device__ __forceinline__ void bar_arrive_release(unsigned* p) {
    asm volatile("red.release.gpu.add.u32 [%0], %1;" :: "l"(p), "r"(1u) : "memory");
}
__device__ __forceinline__ unsigned ld_acquire(unsigned* p) {
    unsigned v;
    asm volatile("ld.acquire.gpu.u32 %0, [%1];" : "=r"(v) : "l"(p) : "memory");
    return v;
}

// ---------------- tf32 helpers ----------------
__device__ __forceinline__ unsigned f2tf(float x) {
    unsigned r;
    asm("cvt.rna.tf32.f32 %0, %1;" : "=r"(r) : "f"(x));
    return r;
}
__device__ __forceinline__ void mma8(float* c, const unsigned* a, const unsigned* b) {
    asm volatile(
        "mma.sync.aligned.m16n8k8.row.col.f32.tf32.tf32.f32 "
        "{%0,%1,%2,%3}, {%4,%5,%6,%7}, {%8,%9}, {%0,%1,%2,%3};"
        : "+f"(c[0]), "+f"(c[1]), "+f"(c[2]), "+f"(c[3])
        : "r"(a[0]), "r"(a[1]), "r"(a[2]), "r"(a[3]), "r"(b[0]), "r"(b[1]));
}

// ---------------- tensor-core GEMM (3xTF32) ----------------
#define SP 132
__global__ __launch_bounds__(256)
void gemm_tc(const float* __restrict__ A, int lda,
             const float* __restrict__ W, int ldw,
             const float* __restrict__ b1, const float* __restrict__ b2,
             float* __restrict__ C, int ldc,
             int M, int N, int K,
             float scale, int act, int causal, int causalK, int trans,
             size_t sA, size_t sW, size_t sC)
{
    int m0 = blockIdx.y * 128;
    int n0 = blockIdx.x * 128;
    if (causal && n0 > m0 + 127) return;
    A += (size_t)blockIdx.z * sA;
    W += (size_t)blockIdx.z * sW;
    C += (size_t)blockIdx.z * sC;
    int Klim = causalK ? min(K, m0 + 128) : K;

    __shared__ float As_hi[16 * SP], As_lo[16 * SP];
    __shared__ float Bs_hi[16 * SP], Bs_lo[16 * SP];

    const int tid = threadIdx.x;
    const int lr = tid >> 1, lq = tid & 1;
    const int kr = tid >> 4, nc = (tid & 15) * 8;
    const int lane = tid & 31;
    const int g = lane >> 2, tg = lane & 3;
    const int wid = tid >> 5;
    const int mBase = (wid & 3) * 32;
    const int nBase = (wid >> 2) * 64;

    float acc[2][8][4];
#pragma unroll
    for (int mt = 0; mt < 2; mt++)
#pragma unroll
        for (int nt = 0; nt < 8; nt++)
#pragma unroll
            for (int i = 0; i < 4; i++) acc[mt][nt][i] = 0.f;

    float4 a4[2], b4[2];

#define LOAD_TILE(K0)                                                          \
    {                                                                          \
        int k0_ = (K0);                                                        \
        const float* ap = A + (size_t)(m0 + lr) * lda;                         \
        _Pragma("unroll")                                                      \
        for (int j = 0; j < 2; j++) {                                          \
            int kb = k0_ + lq * 8 + j * 4;                                     \
            float4 v = make_float4(0.f, 0.f, 0.f, 0.f);                        \
            if (kb + 3 < Klim) v = *(const float4*)(ap + kb);                  \
            else {                                                             \
                if (kb + 0 < Klim) v.x = ap[kb + 0];                           \
                if (kb + 1 < Klim) v.y = ap[kb + 1];                           \
                if (kb + 2 < Klim) v.z = ap[kb + 2];                           \
            }                                                                  \
            a4[j] = v;                                                         \
        }                                                                      \
        if (trans) {                                                           \
            int wr = n0 + lr;                                                  \
            const float* wp = W + (size_t)wr * ldw;                            \
            _Pragma("unroll")                                                  \
            for (int j = 0; j < 2; j++) {                                      \
                int kb = k0_ + lq * 8 + j * 4;                                 \
                float4 v = make_float4(0.f, 0.f, 0.f, 0.f);                    \
                if (wr < N) {                                                  \
                    if (kb + 3 < Klim) v = *(const float4*)(wp + kb);          \
                    else {                                                     \
                        if (kb + 0 < Klim) v.x = wp[kb + 0];                   \
                        if (kb + 1 < Klim) v.y = wp[kb + 1];                   \
                        if (kb + 2 < Klim) v.z = wp[kb + 2];                   \
                    }                                                          \
                }                                                              \
                b4[j] = v;                                                     \
            }                                                                  \
        } else {                                                               \
            int kk = k0_ + kr;                                                 \
            _Pragma("unroll")                                                  \
            for (int j = 0; j < 2; j++) {                                      \
                float4 v = make_float4(0.f, 0.f, 0.f, 0.f);                    \
                if (kk < Klim)                                                 \
                    v = *(const float4*)(W + (size_t)kk * ldw + n0 + nc + j * 4);\
                b4[j] = v;                                                     \
            }                                                                  \
        }                                                                      \
    }

    LOAD_TILE(0);

    for (int k0 = 0; k0 < Klim; k0 += 16) {
#pragma unroll
        for (int j = 0; j < 2; j++) {
            const float* pv = &a4[j].x;
            int kb = lq * 8 + j * 4;
#pragma unroll
            for (int i = 0; i < 4; i++) {
                float a = pv[i];
                float hf = __uint_as_float(f2tf(a));
                As_hi[(kb + i) * SP + lr] = hf;
                As_lo[(kb + i) * SP + lr] = __uint_as_float(f2tf(a - hf));
            }
        }
        if (trans) {
#pragma unroll
            for (int j = 0; j < 2; j++) {
                const float* pv = &b4[j].x;
                int kb = lq * 8 + j * 4;
#pragma unroll
                for (int i = 0; i < 4; i++) {
                    float a = pv[i];
                    float hf = __uint_as_float(f2tf(a));
                    Bs_hi[(kb + i) * SP + lr] = hf;
                    Bs_lo[(kb + i) * SP + lr] = __uint_as_float(f2tf(a - hf));
                }
            }
        } else {
#pragma unroll
            for (int j = 0; j < 2; j++) {
                const float* pv = &b4[j].x;
#pragma unroll
                for (int i = 0; i < 4; i++) {
                    float a = pv[i];
                    float hf = __uint_as_float(f2tf(a));
                    Bs_hi[kr * SP + nc + j * 4 + i] = hf;
                    Bs_lo[kr * SP + nc + j * 4 + i] = __uint_as_float(f2tf(a - hf));
                }
            }
        }
        __syncthreads();

        if (k0 + 16 < Klim) LOAD_TILE(k0 + 16);

#pragma unroll
        for (int kt = 0; kt < 2; kt++) {
            int kr0 = kt * 8 + tg, kr1 = kt * 8 + tg + 4;
            unsigned ah[2][4], al[2][4];
#pragma unroll
            for (int mt = 0; mt < 2; mt++) {
                int m = mBase + mt * 16 + g;
                ah[mt][0] = __float_as_uint(As_hi[kr0 * SP + m]);
                ah[mt][1] = __float_as_uint(As_hi[kr0 * SP + m + 8]);
                ah[mt][2] = __float_as_uint(As_hi[kr1 * SP + m]);
                ah[mt][3] = __float_as_uint(As_hi[kr1 * SP + m + 8]);
                al[mt][0] = __float_as_uint(As_lo[kr0 * SP + m]);
                al[mt][1] = __float_as_uint(As_lo[kr0 * SP + m + 8]);
                al[mt][2] = __float_as_uint(As_lo[kr1 * SP + m]);
                al[mt][3] = __float_as_uint(As_lo[kr1 * SP + m + 8]);
            }
#pragma unroll
            for (int nt = 0; nt < 8; nt++) {
                int n = nBase + nt * 8 + g;
                unsigned bh[2], bl[2];
                bh[0] = __float_as_uint(Bs_hi[kr0 * SP + n]);
                bh[1] = __float_as_uint(Bs_hi[kr1 * SP + n]);
                bl[0] = __float_as_uint(Bs_lo[kr0 * SP + n]);
                bl[1] = __float_as_uint(Bs_lo[kr1 * SP + n]);
#pragma unroll
                for (int mt = 0; mt < 2; mt++) {
                    mma8(acc[mt][nt], ah[mt], bh);
                    mma8(acc[mt][nt], ah[mt], bl);
                    mma8(acc[mt][nt], al[mt], bh);
                }
            }
        }
        __syncthreads();
    }

#pragma unroll
    for (int mt = 0; mt < 2; mt++) {
        int row0 = m0 + mBase + mt * 16 + g;
        int row1 = row0 + 8;
#pragma unroll
        for (int nt = 0; nt < 8; nt++) {
            int col = n0 + nBase + nt * 8 + 2 * tg;
            float bias = 0.f, bias1 = 0.f;
            if (col < N) { if (b1) bias += b1[col]; if (b2) bias += b2[col]; }
            if (col + 1 < N) { if (b1) bias1 += b1[col + 1]; if (b2) bias1 += b2[col + 1]; }
            float v0 = acc[mt][nt][0] * scale + bias;
            float v1 = acc[mt][nt][1] * scale + bias1;
            float v2 = acc[mt][nt][2] * scale + bias;
            float v3 = acc[mt][nt][3] * scale + bias1;
            if (act) { v0 = tanhf(v0); v1 = tanhf(v1); v2 = tanhf(v2); v3 = tanhf(v3); }
            if (col + 1 < N) {
                *(float2*)(C + (size_t)row0 * ldc + col) = make_float2(v0, v1);
                *(float2*)(C + (size_t)row1 * ldc + col) = make_float2(v2, v3);
            } else if (col < N) {
                C[(size_t)row0 * ldc + col] = v0;
                C[(size_t)row1 * ldc + col] = v2;
            }
        }
    }
}

// ---------------- embedding gather ----------------
__global__ void embed_kernel(const int* __restrict__ x, const float* __restrict__ emb,
                             float* __restrict__ X0)
{
    int i = blockIdx.x * 256 + threadIdx.x;
    if (i >= MM * EMB) return;
    int m = i >> 7, e = i & 127;
    X0[(size_t)m * 256 + e] = emb[(size_t)x[m] * EMB + e];
}

// ---------------- pre transpose: [b*L+t][row] -> [t][row][b] ------------
__global__ __launch_bounds__(1024)
void transpose_pre(const float* __restrict__ in, float* __restrict__ out)
{
    __shared__ float tile[32][33];
    int t = blockIdx.x;
    int r0 = blockIdx.y * 32;
    int x = threadIdx.x, y = threadIdx.y;
    tile[y][x] = in[((size_t)y * LL + t) * G4 + r0 + x];
    __syncthreads();
    out[((size_t)t * G4 + r0 + y) * BB + x] = tile[x][y];
}

// ---------------- wavefront state init ----------------
// readers at slot s use parity (s-1)&1; layer l first reads at s=l -> parity (l+1)&1
__global__ void init_wave_state(const float* __restrict__ h_in, float* __restrict__ hS)
{
    int i = blockIdx.x * 256 + threadIdx.x;
    if (i >= NLAYER * HB) return;
    int l = i / HB;
    hS[(size_t)((l + 1) & 1) * NLAYER * HB + i] = h_in[i];
}

// ---------------- wavefront LSTM: all 4 layers, 1027 slots ----------------
// 128 CTAs x 128 thr; layer = blockIdx.x>>5; 12 gate-rows per CTA (3/thread).
__global__ __launch_bounds__(128, 1)
void lstm_wave(const float* __restrict__ preT,   // layer0 pre [t][row][b]
               const float* __restrict__ Whh,    // [4][1536][384]
               const float* __restrict__ WihR,   // [3][1536][384]
               const float* __restrict__ bih, const float* __restrict__ bhh,
               const float* __restrict__ c0,     // [4][B][H]
               float* __restrict__ Y3,           // [B][L][H]
               float* __restrict__ hS,           // [2][4][B][H]
               float* __restrict__ outh, float* __restrict__ outc,
               int writeState)
{
    extern __shared__ float sm[];
    float* hsm = sm;                               // 32 x 196
    float* xsm = sm + 32 * 196;                    // 32 x 196
    float2* sWA = (float2*)(sm + 2 * 32 * 196);    // Whh {i,f}  12x384
    float2* sWB = sWA + 12 * HH;                   // Whh {g,o}
    float2* sXA = sWB + 12 * HH;                   // Wih {i,f}
    float2* sXB = sXA + 12 * HH;

    const int tid = threadIdx.x;
    const int b   = tid & 31;
    const int jl  = tid >> 5;
    const int l   = blockIdx.x >> 5;
    const int sub = blockIdx.x & 31;
    const int jg0 = sub * 12 + jl * 3;

    // ---- stage weights (once) ----
    const float* Whh_l = Whh + (size_t)l * G4 * HH;
    const float* Wih_l = WihR + (size_t)(l - 1) * G4 * HH;   // valid for l>0
    for (int rk = tid; rk < 12 * HH; rk += 128) {
        int row = rk / HH;
        int k   = rk - row * HH;
        int jg  = sub * 12 + row;
        sWA[row * HH + k] = make_float2(Whh_l[(size_t)jg * HH + k],
                                        Whh_l[(size_t)(jg + HH) * HH + k]);
        sWB[row * HH + k] = make_float2(Whh_l[(size_t)(jg + 2 * HH) * HH + k],
                                        Whh_l[(size_t)(jg + 3 * HH) * HH + k]);
        if (l > 0) {
            sXA[row * HH + k] = make_float2(Wih_l[(size_t)jg * HH + k],
                                            Wih_l[(size_t)(jg + HH) * HH + k]);
            sXB[row * HH + k] = make_float2(Wih_l[(size_t)(jg + 2 * HH) * HH + k],
                                            Wih_l[(size_t)(jg + 3 * HH) * HH + k]);
        }
    }

    unsigned long long bIF[3], bGO[3];
    float c_r[3], h_r[3];
#pragma unroll
    for (int r = 0; r < 3; r++) {
        int jg = jg0 + r;
        bIF[r] = pack2(bih[l * G4 + jg] + bhh[l * G4 + jg],
                       bih[l * G4 + HH + jg] + bhh[l * G4 + HH + jg]);
        bGO[r] = pack2(bih[l * G4 + 2 * HH + jg] + bhh[l * G4 + 2 * HH + jg],
                       bih[l * G4 + 3 * HH + jg] + bhh[l * G4 + 3 * HH + jg]);
        c_r[r] = c0[l * HB + b * HH + jg];
        h_r[r] = 0.f;
    }

    const int NS = LL + NLAYER - 1;
    for (int s = 0; s < NS; s++) {
        int t = s - l;
        bool active = (t >= 0) && (t < LL);

        // layer-0: prefetch pre(t) under the barrier wait
        float p[12];
        if (active && l == 0) {
            size_t base = ((size_t)t * G4) * BB + b;
#pragma unroll
            for (int r = 0; r < 3; r++) {
                int jg = jg0 + r;
                p[r * 4 + 0] = __ldcg(&preT[base + (size_t)jg * BB]);
                p[r * 4 + 1] = __ldcg(&preT[base + (size_t)(HH + jg) * BB]);
                p[r * 4 + 2] = __ldcg(&preT[base + (size_t)(2 * HH + jg) * BB]);
                p[r * 4 + 3] = __ldcg(&preT[base + (size_t)(3 * HH + jg) * BB]);
            }
        }

        __syncthreads();
        if (tid == 0) {
            bar_arrive_release(&g_barCount);
            unsigned tgt = (unsigned)NWCTA * (unsigned)(s + 1);
            while (ld_acquire(&g_barCount) < tgt) {}
        }
        __syncthreads();
        if (!active) continue;

        const float4* hsrc = (const float4*)(hS + ((size_t)((s + 1) & 1) * NLAYER + l) * HB);
        const float4* xsrc = (const float4*)(hS + ((size_t)((s + 1) & 1) * NLAYER + (l - 1)) * HB);

        unsigned long long aIF[3], aGO[3];
        if (l == 0) {
#pragma unroll
            for (int r = 0; r < 3; r++) {
                aIF[r] = pack2(p[r * 4 + 0], p[r * 4 + 1]);
                aGO[r] = pack2(p[r * 4 + 2], p[r * 4 + 3]);
            }
        } else {
#pragma unroll
            for (int r = 0; r < 3; r++) { aIF[r] = bIF[r]; aGO[r] = bGO[r]; }
        }

        float4 hreg[12], xreg[12];
        // idx covers (b,k4-half): b = idx/48, k4 = idx%48; src f4 = b*96 + half*48 + k4
#define LOADSTAGE(HALF)                                                        \
        _Pragma("unroll")                                                      \
        for (int i = 0; i < 12; i++) {                                         \
            int idx = tid + i * 128;                                           \
            int bb = idx / 48, kk = idx - bb * 48;                             \
            hreg[i] = __ldcv(hsrc + bb * 96 + (HALF) * 48 + kk);               \
            if (l > 0) xreg[i] = __ldcv(xsrc + bb * 96 + (HALF) * 48 + kk);    \
        }
#define STORESTAGE()                                                           \
        _Pragma("unroll")                                                      \
        for (int i = 0; i < 12; i++) {                                         \
            int idx = tid + i * 128;                                           \
            int bb = idx / 48, kk = idx - bb * 48;                             \
            *(float4*)(hsm + bb * 196 + kk * 4) = hreg[i];                     \
            if (l > 0) *(float4*)(xsm + bb * 196 + kk * 4) = xreg[i];          \
        }
#define COMPUTE(HALF)                                                          \
        if (l == 0) {                                                          \
            _Pragma("unroll 2")                                                \
            for (int k = 0; k < 192; k += 4) {                                 \
                float4 hv = *(const float4*)(hsm + b * 196 + k);               \
                unsigned long long hh0 = pack2(hv.x, hv.x), hh1 = pack2(hv.y, hv.y); \
                unsigned long long hh2 = pack2(hv.z, hv.z), hh3 = pack2(hv.w, hv.w); \
                _Pragma("unroll")                                              \
                for (int r = 0; r < 3; r++) {                                  \
                    const float2* wa = sWA + (jl * 3 + r) * HH + (HALF) * 192 + k; \
                    const float2* wb = sWB + (jl * 3 + r) * HH + (HALF) * 192 + k; \
                    ulonglong2 A0 = *(const ulonglong2*)(wa);                  \
                    ulonglong2 A1 = *(const ulonglong2*)(wa + 2);              \
                    ulonglong2 B0 = *(const ulonglong2*)(wb);                  \
                    ulonglong2 B1 = *(const ulonglong2*)(wb + 2);              \
                    fma2(aIF[r], A0.x, hh0); fma2(aGO[r], B0.x, hh0);          \
                    fma2(aIF[r], A0.y, hh1); fma2(aGO[r], B0.y, hh1);          \
                    fma2(aIF[r], A1.x, hh2); fma2(aGO[r], B1.x, hh2);          \
                    fma2(aIF[r], A1.y, hh3); fma2(aGO[r], B1.y, hh3);          \
                }                                                              \
            }                                                                  \
        } else {                                                               \
            _Pragma("unroll 2")                                                \
            for (int k = 0; k < 192; k += 4) {                                 \
                float4 hv = *(const float4*)(hsm + b * 196 + k);               \
                float4 xv = *(const float4*)(xsm + b * 196 + k);               \
                unsigned long long hh0 = pack2(hv.x, hv.x), hh1 = pack2(hv.y, hv.y); \
                unsigned long long hh2 = pack2(hv.z, hv.z), hh3 = pack2(hv.w, hv.w); \
                unsigned long long xx0 = pack2(xv.x, xv.x), xx1 = pack2(xv.y, xv.y); \
                unsigned long long xx2 = pack2(xv.z, xv.z), xx3 = pack2(xv.w, xv.w); \
                _Pragma("unroll")                                              \
                for (int r = 0; r < 3; r++) {                                  \
                    int wo = (jl * 3 + r) * HH + (HALF) * 192 + k;             \
                    ulonglong2 A0 = *(const ulonglong2*)(sWA + wo);            \
                    ulonglong2 A1 = *(const ulonglong2*)(sWA + wo + 2);        \
                    ulonglong2 B0 = *(const ulonglong2*)(sWB + wo);            \
                    ulonglong2 B1 = *(const ulonglong2*)(sWB + wo + 2);        \
                    ulonglong2 C0 = *(const ulonglong2*)(sXA + wo);            \
                    ulonglong2 C1 = *(const ulonglong2*)(sXA + wo + 2);        \
                    ulonglong2 D0 = *(const ulonglong2*)(sXB + wo);            \
                    ulonglong2 D1 = *(const ulonglong2*)(sXB + wo + 2);        \
                    fma2(aIF[r], A0.x, hh0); fma2(aGO[r], B0.x, hh0);          \
                    fma2(aIF[r], A0.y, hh1); fma2(aGO[r], B0.y, hh1);          \
                    fma2(aIF[r], A1.x, hh2); fma2(aGO[r], B1.x, hh2);          \
                    fma2(aIF[r], A1.y, hh3); fma2(aGO[r], B1.y, hh3);          \
                    fma2(aIF[r], C0.x, xx0); fma2(aGO[r], D0.x, xx0);          \
                    fma2(aIF[r], C0.y, xx1); fma2(aGO[r], D0.y, xx1);          \
                    fma2(aIF[r], C1.x, xx2); fma2(aGO[r], D1.x, xx2);          \
                    fma2(aIF[r], C1.y, xx3); fma2(aGO[r], D1.y, xx3);          \
                }                                                              \
            }                                                                  \
        }

        LOADSTAGE(0)
        STORESTAGE()
        __syncthreads();
        LOADSTAGE(1)          // hi-half LDG latency hides under lo compute
        COMPUTE(0)
        __syncthreads();
        STORESTAGE()
        __syncthreads();
        COMPUTE(1)

        // epilogue
        float* hdst = hS + ((size_t)(s & 1) * NLAYER + l) * HB + b * HH;
#pragma unroll
        for (int r = 0; r < 3; r++) {
            float gi, gf, gg_, go;
            unpack2(aIF[r], gi, gf);
            unpack2(aGO[r], gg_, go);
            float ig = 1.f / (1.f + expf(-gi));
            float fg = 1.f / (1.f + expf(-gf));
            float G  = tanhf(gg_);
            float og = 1.f / (1.f + expf(-go));
            c_r[r] = fg * c_r[r] + ig * G;
            h_r[r] = og * tanhf(c_r[r]);
            hdst[jg0 + r] = h_r[r];
            if (l == 3) Y3[((size_t)b * LL + t) * HH + jg0 + r] = h_r[r];
        }
    }

    if (writeState) {
#pragma unroll
        for (int r = 0; r < 3; r++) {
            outh[l * HB + b * HH + jg0 + r] = h_r[r];
            outc[l * HB + b * HH + jg0 + r] = c_r[r];
        }
    }
}

// ---------------- causal softmax ----------------
__global__ __launch_bounds__(256)
void softmax_causal(float* __restrict__ S)
{
    int bq = blockIdx.x;
    int b = bq >> 10, q = bq & 1023;
    float* row = S + ((size_t)b * LL + q) * LL;
    int len = q + 1;
    int tid = threadIdx.x;
    __shared__ float red[256];

    float mx = -1e30f;
    for (int k = tid; k < len; k += 256) mx = fmaxf(mx, row[k]);
    red[tid] = mx; __syncthreads();
    for (int s = 128; s > 0; s >>= 1) {
        if (tid < s) red[tid] = fmaxf(red[tid], red[tid + s]);
        __syncthreads();
    }
    mx = red[0]; __syncthreads();

    float sum = 0.f;
    for (int k = tid; k < len; k += 256) sum += expf(row[k] - mx);
    red[tid] = sum; __syncthreads();
    for (int s = 128; s > 0; s >>= 1) {
        if (tid < s) red[tid] += red[tid + s];
        __syncthreads();
    }
    sum = red[0]; __syncthreads();

    float inv = 1.f / sum;
    for (int k = tid; k < LL; k += 256)
        row[k] = (k < len) ? expf(row[k] - mx) * inv : 0.f;
}

// ---------------- concat [out | ctx] ----------------
__global__ void concat_kernel(const float* __restrict__ Yout, const float* __restrict__ ctx,
                              float* __restrict__ cat)
{
    int i = blockIdx.x * 256 + threadIdx.x;
    if (i >= MM * 2 * HH) return;
    int m = i / (2 * HH), j = i % (2 * HH);
    cat[i] = (j < HH) ? Yout[(size_t)m * HH + j] : ctx[(size_t)m * HH + j - HH];
}

// ---------------- host ----------------
extern "C" void kernel_launch(void* const* d_in, const int* in_sizes, int n_in,
                              void* d_out, int out_size)
{
    const int*   x       = (const int*)d_in[0];
    const float* context = (const float*)d_in[1];
    const float* h_in    = (const float*)d_in[2];
    const float* c_in    = (const float*)d_in[3];
    const float* emb     = (const float*)d_in[4];
    const float* ctx_W   = (const float*)d_in[5];
    const float* ctx_b   = (const float*)d_in[6];
    const float* Wih0    = (const float*)d_in[7];
    const float* WihR    = (const float*)d_in[8];
    const float* Whh     = (const float*)d_in[9];
    const float* bih     = (const float*)d_in[10];
    const float* bhh     = (const float*)d_in[11];
    const float* Wa      = (const float*)d_in[12];
    const float* comb_W  = (const float*)d_in[13];
    const float* comb_b  = (const float*)d_in[14];
    const float* fc_W    = (const float*)d_in[15];
    const float* fc_b    = (const float*)d_in[16];
    float* out = (float*)d_out;

    float *x0, *Y3, *pre, *preT, *keys, *scores, *cat, *comb, *hS;
    unsigned* barCount;
    cudaGetSymbolAddress((void**)&x0,       g_x0);
    cudaGetSymbolAddress((void**)&Y3,       g_seqB);
    cudaGetSymbolAddress((void**)&pre,      g_pre);
    cudaGetSymbolAddress((void**)&preT,     g_preT);
    cudaGetSymbolAddress((void**)&keys,     g_keys);
    cudaGetSymbolAddress((void**)&scores,   g_scores);
    cudaGetSymbolAddress((void**)&cat,      g_cat);
    cudaGetSymbolAddress((void**)&comb,     g_comb);
    cudaGetSymbolAddress((void**)&hS,       g_hS);
    cudaGetSymbolAddress((void**)&barCount, g_barCount);

    const int waveSmem = (2 * 32 * 196 + 4 * 12 * HH * 2) * 4;   // 197,632 B
    cudaFuncSetAttribute(lstm_wave, cudaFuncAttributeMaxDynamicSharedMemorySize, waveSmem);

    const int logitsN = MM * NVOCAB;
    const bool wantState = (out_size >= logitsN + 2 * NLAYER * BB * HH);
    float* outh = out + logitsN;
    float* outc = out + logitsN + NLAYER * BB * HH;

    // 1) embedding + context projection -> x0 [M,256]
    embed_kernel<<<(MM * EMB + 255) / 256, 256>>>(x, emb, x0);
    gemm_tc<<<dim3(1, 256, 1), 256>>>(context, CTXIN, ctx_W, CTXIN, ctx_b, nullptr,
                                      x0 + EMB, 2 * EMB, MM, EMB, CTXIN,
                                      1.f, 0, 0, 0, 1, 0, 0, 0);

    // 2) layer-0 input projection + transpose, then 4-layer wavefront
    gemm_tc<<<dim3(G4 / 128, MM / 128, 1), 256>>>(x0, 2 * EMB, Wih0, 2 * EMB,
                                                  bih, bhh, pre, G4, MM, G4, 2 * EMB,
                                                  1.f, 0, 0, 0, 1, 0, 0, 0);
    transpose_pre<<<dim3(LL, G4 / 32), dim3(32, 32)>>>(pre, preT);
    init_wave_state<<<(NLAYER * HB + 255) / 256, 256>>>(h_in, hS);
    cudaMemsetAsync(barCount, 0, sizeof(unsigned));
    lstm_wave<<<NWCTA, 128, waveSmem>>>(preT, Whh, WihR, bih, bhh, c_in,
                                        Y3, hS, outh, outc, wantState ? 1 : 0);

    // 3) attention
    gemm_tc<<<dim3(HH / 128, MM / 128, 1), 256>>>(Y3, HH, Wa, HH, nullptr, nullptr,
                                                  keys, HH, MM, HH, HH,
                                                  1.f, 0, 0, 0, 1, 0, 0, 0);
    float invs = 1.f / sqrtf((float)HH);
    gemm_tc<<<dim3(8, 8, 32), 256>>>(Y3, HH, keys, HH, nullptr, nullptr,
                                     scores, LL, LL, LL, HH,
                                     invs, 0, 1, 0, 1,
                                     (size_t)LL * HH, (size_t)LL * HH, (size_t)LL * LL);
    softmax_causal<<<BB * LL, 256>>>(scores);
    gemm_tc<<<dim3(HH / 128, 8, 32), 256>>>(scores, LL, Y3, HH, nullptr, nullptr,
                                            keys, HH, LL, HH, LL,
                                            1.f, 0, 0, 1, 0,
                                            (size_t)LL * LL, (size_t)LL * HH, (size_t)LL * HH);

    // 4) combine + output head
    concat_kernel<<<(MM * 2 * HH + 255) / 256, 256>>>(Y3, keys, cat);
    gemm_tc<<<dim3(HH / 128, MM / 128, 1), 256>>>(cat, 2 * HH, comb_W, 2 * HH,
                                                  comb_b, nullptr, comb, HH,
                                                  MM, HH, 2 * HH,
                                                  1.f, 1, 0, 0, 1, 0, 0, 0);
    gemm_tc<<<dim3(1, MM / 128, 1), 256>>>(comb, HH, fc_W, HH, fc_b, nullptr,
                                           out, NVOCAB, MM, NVOCAB, HH,
                                           1.f, 0, 0, 0, 1, 0, 0, 0);
}

// round 12
// speedup vs baseline: 1.5903x; 1.0785x over previous
#include <cuda_runtime.h>
#include <cuda_bf16.h>
#include <math.h>

#define BB 32
#define LL 1024
#define EMB 128
#define HH 384
#define NLAYER 4
#define NVOCAB 100
#define G4 (4*HH)
#define MM (BB*LL)
#define CTXIN 300
#define HB (HH*BB)
#define NWCTA 128          // wavefront CTAs (32 per layer)

// ---------------- static scratch ----------------
__device__ float g_x0[MM * 2 * EMB];
__device__ float g_seqB[MM * HH];               // Y3 [B,L,H]
__device__ float g_pre[(size_t)MM * G4];
__device__ float g_preT[(size_t)MM * G4];       // [t][row][b]
__device__ float g_keys[MM * HH];
__device__ float g_scores[(size_t)BB * LL * LL];
__device__ float g_cat[MM * 2 * HH];
__device__ float g_comb[MM * HH];
__device__ float g_hS[2 * NLAYER * HB];         // wavefront state [parity][l][b][k]
__device__ unsigned g_barCount;

// ---------------- f32x2 packed-FMA helpers ----------------
__device__ __forceinline__ void fma2(unsigned long long& acc,
                                     unsigned long long a, unsigned long long b) {
    asm("fma.rn.f32x2 %0, %1, %2, %0;" : "+l"(acc) : "l"(a), "l"(b));
}
__device__ __forceinline__ unsigned long long pack2(float x, float y) {
    unsigned long long r;
    asm("mov.b64 %0, {%1, %2};" : "=l"(r) : "f"(x), "f"(y));
    return r;
}
__device__ __forceinline__ void unpack2(unsigned long long v, float& x, float& y) {
    asm("mov.b64 {%0, %1}, %2;" : "=f"(x), "=f"(y) : "l"(v));
}
__device__ __forceinline__ void bar_arrive_release(unsigned* p) {
    asm volatile("red.release.gpu.add.u32 [%0], %1;" :: "l"(p), "r"(1u) : "memory");
}
__device__ __forceinline__ unsigned ld_acquire(unsigned* p) {
    unsigned v;
    asm volatile("ld.acquire.gpu.u32 %0, [%1];" : "=r"(v) : "l"(p) : "memory");
    return v;
}

// ---------------- bf16 split helpers ----------------
// pack two floats to bf16x2: low 16 bits = lo_val (k even), high = hi_val (k odd)
__device__ __forceinline__ unsigned pkbf2(float lo_val, float hi_val) {
    unsigned r;
    asm("cvt.rn.bf16x2.f32 %0, %1, %2;" : "=r"(r) : "f"(hi_val), "f"(lo_val));
    return r;
}
__device__ __forceinline__ float bfhi(float x) {
    return __bfloat162float(__float2bfloat16_rn(x));
}
// m16n8k16 bf16 mma, fp32 accum
__device__ __forceinline__ void mma16(float* c, const unsigned* a, const unsigned* b) {
    asm volatile(
        "mma.sync.aligned.m16n8k16.row.col.f32.bf16.bf16.f32 "
        "{%0,%1,%2,%3}, {%4,%5,%6,%7}, {%8,%9}, {%0,%1,%2,%3};"
        : "+f"(c[0]), "+f"(c[1]), "+f"(c[2]), "+f"(c[3])
        : "r"(a[0]), "r"(a[1]), "r"(a[2]), "r"(a[3]), "r"(b[0]), "r"(b[1]));
}

// ---------------- tensor-core GEMM (3-pass split-bf16, ~1e-5 accuracy) -----
// C = act(scale * (A @ OP) + b1 + b2)
//   trans=1: OP = W^T, W[N,K] row-major.  trans=0: OP = B, B[K,N] row-major
//            (trans=0 requires N multiple of 128).
// smem layout: [k-pair 0..7][row 0..127] packed bf16x2, pitch SPB=136 b32
// (bank = 8*kpair + row -> conflict-free fragment loads).
#define SPB 136
__global__ __launch_bounds__(256)
void gemm_tc(const float* __restrict__ A, int lda,
             const float* __restrict__ W, int ldw,
             const float* __restrict__ b1, const float* __restrict__ b2,
             float* __restrict__ C, int ldc,
             int M, int N, int K,
             float scale, int act, int causal, int causalK, int trans,
             size_t sA, size_t sW, size_t sC)
{
    int m0 = blockIdx.y * 128;
    int n0 = blockIdx.x * 128;
    if (causal && n0 > m0 + 127) return;
    A += (size_t)blockIdx.z * sA;
    W += (size_t)blockIdx.z * sW;
    C += (size_t)blockIdx.z * sC;
    int Klim = causalK ? min(K, m0 + 128) : K;

    __shared__ unsigned As_hi[8 * SPB], As_lo[8 * SPB];
    __shared__ unsigned Bs_hi[8 * SPB], Bs_lo[8 * SPB];

    const int tid = threadIdx.x;
    const int lr = tid >> 1, lq = tid & 1;         // A / W-trans staging
    const int pB = tid >> 5, nq = (tid & 31) * 4;  // B no-trans staging
    const int lane = tid & 31;
    const int g = lane >> 2, tg = lane & 3;
    const int wid = tid >> 5;
    const int mBase = (wid & 3) * 32;
    const int nBase = (wid >> 2) * 64;

    float acc[2][8][4];
#pragma unroll
    for (int mt = 0; mt < 2; mt++)
#pragma unroll
        for (int nt = 0; nt < 8; nt++)
#pragma unroll
            for (int i = 0; i < 4; i++) acc[mt][nt][i] = 0.f;

    float4 a4[2], b4[2];

#define LOAD_TILE(K0)                                                          \
    {                                                                          \
        int k0_ = (K0);                                                        \
        const float* ap = A + (size_t)(m0 + lr) * lda;                         \
        _Pragma("unroll")                                                      \
        for (int j = 0; j < 2; j++) {                                          \
            int kb = k0_ + lq * 8 + j * 4;                                     \
            float4 v = make_float4(0.f, 0.f, 0.f, 0.f);                        \
            if (kb + 3 < Klim) v = *(const float4*)(ap + kb);                  \
            else {                                                             \
                if (kb + 0 < Klim) v.x = ap[kb + 0];                           \
                if (kb + 1 < Klim) v.y = ap[kb + 1];                           \
                if (kb + 2 < Klim) v.z = ap[kb + 2];                           \
            }                                                                  \
            a4[j] = v;                                                         \
        }                                                                      \
        if (trans) {                                                           \
            int wr = n0 + lr;                                                  \
            const float* wp = W + (size_t)wr * ldw;                            \
            _Pragma("unroll")                                                  \
            for (int j = 0; j < 2; j++) {                                      \
                int kb = k0_ + lq * 8 + j * 4;                                 \
                float4 v = make_float4(0.f, 0.f, 0.f, 0.f);                    \
                if (wr < N) {                                                  \
                    if (kb + 3 < Klim) v = *(const float4*)(wp + kb);          \
                    else {                                                     \
                        if (kb + 0 < Klim) v.x = wp[kb + 0];                   \
                        if (kb + 1 < Klim) v.y = wp[kb + 1];                   \
                        if (kb + 2 < Klim) v.z = wp[kb + 2];                   \
                    }                                                          \
                }                                                              \
                b4[j] = v;                                                     \
            }                                                                  \
        } else {                                                               \
            int kk0 = k0_ + 2 * pB;                                            \
            int kk1 = kk0 + 1;                                                 \
            b4[0] = (kk0 < Klim)                                               \
                  ? *(const float4*)(W + (size_t)kk0 * ldw + n0 + nq)          \
                  : make_float4(0.f, 0.f, 0.f, 0.f);                           \
            b4[1] = (kk1 < Klim)                                               \
                  ? *(const float4*)(W + (size_t)kk1 * ldw + n0 + nq)          \
                  : make_float4(0.f, 0.f, 0.f, 0.f);                           \
        }                                                                      \
    }

    LOAD_TILE(0);

    for (int k0 = 0; k0 < Klim; k0 += 16) {
        // ---- convert & store staged regs to smem (hi/lo bf16x2 split) ----
#pragma unroll
        for (int j = 0; j < 2; j++) {
            float4 e = a4[j];
            int kp = lq * 4 + j * 2;
            float hx = bfhi(e.x), hy = bfhi(e.y), hz = bfhi(e.z), hw = bfhi(e.w);
            As_hi[kp * SPB + lr]       = pkbf2(hx, hy);
            As_hi[(kp + 1) * SPB + lr] = pkbf2(hz, hw);
            As_lo[kp * SPB + lr]       = pkbf2(e.x - hx, e.y - hy);
            As_lo[(kp + 1) * SPB + lr] = pkbf2(e.z - hz, e.w - hw);
        }
        if (trans) {
#pragma unroll
            for (int j = 0; j < 2; j++) {
                float4 e = b4[j];
                int kp = lq * 4 + j * 2;
                float hx = bfhi(e.x), hy = bfhi(e.y), hz = bfhi(e.z), hw = bfhi(e.w);
                Bs_hi[kp * SPB + lr]       = pkbf2(hx, hy);
                Bs_hi[(kp + 1) * SPB + lr] = pkbf2(hz, hw);
                Bs_lo[kp * SPB + lr]       = pkbf2(e.x - hx, e.y - hy);
                Bs_lo[(kp + 1) * SPB + lr] = pkbf2(e.z - hz, e.w - hw);
            }
        } else {
            // rows 2p (k even) in b4[0], 2p+1 (k odd) in b4[1]; pack across rows
            const float* r0 = &b4[0].x;
            const float* r1 = &b4[1].x;
            unsigned hi4[4], lo4[4];
#pragma unroll
            for (int i = 0; i < 4; i++) {
                float h0 = bfhi(r0[i]), h1 = bfhi(r1[i]);
                hi4[i] = pkbf2(h0, h1);
                lo4[i] = pkbf2(r0[i] - h0, r1[i] - h1);
            }
            *(uint4*)(Bs_hi + pB * SPB + nq) = make_uint4(hi4[0], hi4[1], hi4[2], hi4[3]);
            *(uint4*)(Bs_lo + pB * SPB + nq) = make_uint4(lo4[0], lo4[1], lo4[2], lo4[3]);
        }
        __syncthreads();

        if (k0 + 16 < Klim) LOAD_TILE(k0 + 16);

        // ---- fragments + mma (m16n8k16, 3 passes) ----
        unsigned ah[2][4], al[2][4];
#pragma unroll
        for (int mt = 0; mt < 2; mt++) {
            int m = mBase + mt * 16 + g;
            ah[mt][0] = As_hi[tg * SPB + m];
            ah[mt][1] = As_hi[tg * SPB + m + 8];
            ah[mt][2] = As_hi[(tg + 4) * SPB + m];
            ah[mt][3] = As_hi[(tg + 4) * SPB + m + 8];
            al[mt][0] = As_lo[tg * SPB + m];
            al[mt][1] = As_lo[tg * SPB + m + 8];
            al[mt][2] = As_lo[(tg + 4) * SPB + m];
            al[mt][3] = As_lo[(tg + 4) * SPB + m + 8];
        }
#pragma unroll
        for (int nt = 0; nt < 8; nt++) {
            int n = nBase + nt * 8 + g;
            unsigned bh[2], bl[2];
            bh[0] = Bs_hi[tg * SPB + n];
            bh[1] = Bs_hi[(tg + 4) * SPB + n];
            bl[0] = Bs_lo[tg * SPB + n];
            bl[1] = Bs_lo[(tg + 4) * SPB + n];
#pragma unroll
            for (int mt = 0; mt < 2; mt++) {
                mma16(acc[mt][nt], ah[mt], bh);
                mma16(acc[mt][nt], ah[mt], bl);
                mma16(acc[mt][nt], al[mt], bh);
            }
        }
        __syncthreads();
    }

    // ---- epilogue ----
#pragma unroll
    for (int mt = 0; mt < 2; mt++) {
        int row0 = m0 + mBase + mt * 16 + g;
        int row1 = row0 + 8;
#pragma unroll
        for (int nt = 0; nt < 8; nt++) {
            int col = n0 + nBase + nt * 8 + 2 * tg;
            float bias = 0.f, bias1 = 0.f;
            if (col < N) { if (b1) bias += b1[col]; if (b2) bias += b2[col]; }
            if (col + 1 < N) { if (b1) bias1 += b1[col + 1]; if (b2) bias1 += b2[col + 1]; }
            float v0 = acc[mt][nt][0] * scale + bias;
            float v1 = acc[mt][nt][1] * scale + bias1;
            float v2 = acc[mt][nt][2] * scale + bias;
            float v3 = acc[mt][nt][3] * scale + bias1;
            if (act) { v0 = tanhf(v0); v1 = tanhf(v1); v2 = tanhf(v2); v3 = tanhf(v3); }
            if (col + 1 < N) {
                *(float2*)(C + (size_t)row0 * ldc + col) = make_float2(v0, v1);
                *(float2*)(C + (size_t)row1 * ldc + col) = make_float2(v2, v3);
            } else if (col < N) {
                C[(size_t)row0 * ldc + col] = v0;
                C[(size_t)row1 * ldc + col] = v2;
            }
        }
    }
}

// ---------------- embedding gather ----------------
__global__ void embed_kernel(const int* __restrict__ x, const float* __restrict__ emb,
                             float* __restrict__ X0)
{
    int i = blockIdx.x * 256 + threadIdx.x;
    if (i >= MM * EMB) return;
    int m = i >> 7, e = i & 127;
    X0[(size_t)m * 256 + e] = emb[(size_t)x[m] * EMB + e];
}

// ---------------- pre transpose: [b*L+t][row] -> [t][row][b] ------------
__global__ __launch_bounds__(1024)
void transpose_pre(const float* __restrict__ in, float* __restrict__ out)
{
    __shared__ float tile[32][33];
    int t = blockIdx.x;
    int r0 = blockIdx.y * 32;
    int x = threadIdx.x, y = threadIdx.y;
    tile[y][x] = in[((size_t)y * LL + t) * G4 + r0 + x];
    __syncthreads();
    out[((size_t)t * G4 + r0 + y) * BB + x] = tile[x][y];
}

// ---------------- wavefront state init ----------------
__global__ void init_wave_state(const float* __restrict__ h_in, float* __restrict__ hS)
{
    int i = blockIdx.x * 256 + threadIdx.x;
    if (i >= NLAYER * HB) return;
    int l = i / HB;
    hS[(size_t)((l + 1) & 1) * NLAYER * HB + i] = h_in[i];
}

// ---------------- wavefront LSTM: all 4 layers, 1027 slots ----------------
__global__ __launch_bounds__(128, 1)
void lstm_wave(const float* __restrict__ preT,   // layer0 pre [t][row][b]
               const float* __restrict__ Whh,    // [4][1536][384]
               const float* __restrict__ WihR,   // [3][1536][384]
               const float* __restrict__ bih, const float* __restrict__ bhh,
               const float* __restrict__ c0,     // [4][B][H]
               float* __restrict__ Y3,           // [B][L][H]
               float* __restrict__ hS,           // [2][4][B][H]
               float* __restrict__ outh, float* __restrict__ outc,
               int writeState)
{
    extern __shared__ float sm[];
    float* hsm = sm;                               // 32 x 196
    float* xsm = sm + 32 * 196;                    // 32 x 196
    float2* sWA = (float2*)(sm + 2 * 32 * 196);    // Whh {i,f}  12x384
    float2* sWB = sWA + 12 * HH;                   // Whh {g,o}
    float2* sXA = sWB + 12 * HH;                   // Wih {i,f}
    float2* sXB = sXA + 12 * HH;

    const int tid = threadIdx.x;
    const int b   = tid & 31;
    const int jl  = tid >> 5;
    const int l   = blockIdx.x >> 5;
    const int sub = blockIdx.x & 31;
    const int jg0 = sub * 12 + jl * 3;

    const float* Whh_l = Whh + (size_t)l * G4 * HH;
    const float* Wih_l = WihR + (size_t)(l - 1) * G4 * HH;
    for (int rk = tid; rk < 12 * HH; rk += 128) {
        int row = rk / HH;
        int k   = rk - row * HH;
        int jg  = sub * 12 + row;
        sWA[row * HH + k] = make_float2(Whh_l[(size_t)jg * HH + k],
                                        Whh_l[(size_t)(jg + HH) * HH + k]);
        sWB[row * HH + k] = make_float2(Whh_l[(size_t)(jg + 2 * HH) * HH + k],
                                        Whh_l[(size_t)(jg + 3 * HH) * HH + k]);
        if (l > 0) {
            sXA[row * HH + k] = make_float2(Wih_l[(size_t)jg * HH + k],
                                            Wih_l[(size_t)(jg + HH) * HH + k]);
            sXB[row * HH + k] = make_float2(Wih_l[(size_t)(jg + 2 * HH) * HH + k],
                                            Wih_l[(size_t)(jg + 3 * HH) * HH + k]);
        }
    }

    unsigned long long bIF[3], bGO[3];
    float c_r[3], h_r[3];
#pragma unroll
    for (int r = 0; r < 3; r++) {
        int jg = jg0 + r;
        bIF[r] = pack2(bih[l * G4 + jg] + bhh[l * G4 + jg],
                       bih[l * G4 + HH + jg] + bhh[l * G4 + HH + jg]);
        bGO[r] = pack2(bih[l * G4 + 2 * HH + jg] + bhh[l * G4 + 2 * HH + jg],
                       bih[l * G4 + 3 * HH + jg] + bhh[l * G4 + 3 * HH + jg]);
        c_r[r] = c0[l * HB + b * HH + jg];
        h_r[r] = 0.f;
    }

    const int NS = LL + NLAYER - 1;
    for (int s = 0; s < NS; s++) {
        int t = s - l;
        bool active = (t >= 0) && (t < LL);

        float p[12];
        if (active && l == 0) {
            size_t base = ((size_t)t * G4) * BB + b;
#pragma unroll
            for (int r = 0; r < 3; r++) {
                int jg = jg0 + r;
                p[r * 4 + 0] = __ldcg(&preT[base + (size_t)jg * BB]);
                p[r * 4 + 1] = __ldcg(&preT[base + (size_t)(HH + jg) * BB]);
                p[r * 4 + 2] = __ldcg(&preT[base + (size_t)(2 * HH + jg) * BB]);
                p[r * 4 + 3] = __ldcg(&preT[base + (size_t)(3 * HH + jg) * BB]);
            }
        }

        __syncthreads();
        if (tid == 0) {
            bar_arrive_release(&g_barCount);
            unsigned tgt = (unsigned)NWCTA * (unsigned)(s + 1);
            while (ld_acquire(&g_barCount) < tgt) {}
        }
        __syncthreads();
        if (!active) continue;

        const float4* hsrc = (const float4*)(hS + ((size_t)((s + 1) & 1) * NLAYER + l) * HB);
        const float4* xsrc = (const float4*)(hS + ((size_t)((s + 1) & 1) * NLAYER + (l - 1)) * HB);

        unsigned long long aIF[3], aGO[3];
        if (l == 0) {
#pragma unroll
            for (int r = 0; r < 3; r++) {
                aIF[r] = pack2(p[r * 4 + 0], p[r * 4 + 1]);
                aGO[r] = pack2(p[r * 4 + 2], p[r * 4 + 3]);
            }
        } else {
#pragma unroll
            for (int r = 0; r < 3; r++) { aIF[r] = bIF[r]; aGO[r] = bGO[r]; }
        }

        float4 hreg[12], xreg[12];
#define LOADSTAGE(HALF)                                                        \
        _Pragma("unroll")                                                      \
        for (int i = 0; i < 12; i++) {                                         \
            int idx = tid + i * 128;                                           \
            int bb = idx / 48, kk = idx - bb * 48;                             \
            hreg[i] = __ldcv(hsrc + bb * 96 + (HALF) * 48 + kk);               \
            if (l > 0) xreg[i] = __ldcv(xsrc + bb * 96 + (HALF) * 48 + kk);    \
        }
#define STORESTAGE()                                                           \
        _Pragma("unroll")                                                      \
        for (int i = 0; i < 12; i++) {                                         \
            int idx = tid + i * 128;                                           \
            int bb = idx / 48, kk = idx - bb * 48;                             \
            *(float4*)(hsm + bb * 196 + kk * 4) = hreg[i];                     \
            if (l > 0) *(float4*)(xsm + bb * 196 + kk * 4) = xreg[i];          \
        }
#define COMPUTE(HALF)                                                          \
        if (l == 0) {                                                          \
            _Pragma("unroll 2")                                                \
            for (int k = 0; k < 192; k += 4) {                                 \
                float4 hv = *(const float4*)(hsm + b * 196 + k);               \
                unsigned long long hh0 = pack2(hv.x, hv.x), hh1 = pack2(hv.y, hv.y); \
                unsigned long long hh2 = pack2(hv.z, hv.z), hh3 = pack2(hv.w, hv.w); \
                _Pragma("unroll")                                              \
                for (int r = 0; r < 3; r++) {                                  \
                    const float2* wa = sWA + (jl * 3 + r) * HH + (HALF) * 192 + k; \
                    const float2* wb = sWB + (jl * 3 + r) * HH + (HALF) * 192 + k; \
                    ulonglong2 A0 = *(const ulonglong2*)(wa);                  \
                    ulonglong2 A1 = *(const ulonglong2*)(wa + 2);              \
                    ulonglong2 B0 = *(const ulonglong2*)(wb);                  \
                    ulonglong2 B1 = *(const ulonglong2*)(wb + 2);              \
                    fma2(aIF[r], A0.x, hh0); fma2(aGO[r], B0.x, hh0);          \
                    fma2(aIF[r], A0.y, hh1); fma2(aGO[r], B0.y, hh1);          \
                    fma2(aIF[r], A1.x, hh2); fma2(aGO[r], B1.x, hh2);          \
                    fma2(aIF[r], A1.y, hh3); fma2(aGO[r], B1.y, hh3);          \
                }                                                              \
            }                                                                  \
        } else {                                                               \
            _Pragma("unroll 2")                                                \
            for (int k = 0; k < 192; k += 4) {                                 \
                float4 hv = *(const float4*)(hsm + b * 196 + k);               \
                float4 xv = *(const float4*)(xsm + b * 196 + k);               \
                unsigned long long hh0 = pack2(hv.x, hv.x), hh1 = pack2(hv.y, hv.y); \
                unsigned long long hh2 = pack2(hv.z, hv.z), hh3 = pack2(hv.w, hv.w); \
                unsigned long long xx0 = pack2(xv.x, xv.x), xx1 = pack2(xv.y, xv.y); \
                unsigned long long xx2 = pack2(xv.z, xv.z), xx3 = pack2(xv.w, xv.w); \
                _Pragma("unroll")                                              \
                for (int r = 0; r < 3; r++) {                                  \
                    int wo = (jl * 3 + r) * HH + (HALF) * 192 + k;             \
                    ulonglong2 A0 = *(const ulonglong2*)(sWA + wo);            \
                    ulonglong2 A1 = *(const ulonglong2*)(sWA + wo + 2);        \
                    ulonglong2 B0 = *(const ulonglong2*)(sWB + wo);            \
                    ulonglong2 B1 = *(const ulonglong2*)(sWB + wo + 2);        \
                    ulonglong2 C0 = *(const ulonglong2*)(sXA + wo);            \
                    ulonglong2 C1 = *(const ulonglong2*)(sXA + wo + 2);        \
                    ulonglong2 D0 = *(const ulonglong2*)(sXB + wo);            \
                    ulonglong2 D1 = *(const ulonglong2*)(sXB + wo + 2);        \
                    fma2(aIF[r], A0.x, hh0); fma2(aGO[r], B0.x, hh0);          \
                    fma2(aIF[r], A0.y, hh1); fma2(aGO[r], B0.y, hh1);          \
                    fma2(aIF[r], A1.x, hh2); fma2(aGO[r], B1.x, hh2);          \
                    fma2(aIF[r], A1.y, hh3); fma2(aGO[r], B1.y, hh3);          \
                    fma2(aIF[r], C0.x, xx0); fma2(aGO[r], D0.x, xx0);          \
                    fma2(aIF[r], C0.y, xx1); fma2(aGO[r], D0.y, xx1);          \
                    fma2(aIF[r], C1.x, xx2); fma2(aGO[r], D1.x, xx2);          \
                    fma2(aIF[r], C1.y, xx3); fma2(aGO[r], D1.y, xx3);          \
                }                                                              \
            }                                                                  \
        }

        LOADSTAGE(0)
        STORESTAGE()
        __syncthreads();
        LOADSTAGE(1)
        COMPUTE(0)
        __syncthreads();
        STORESTAGE()
        __syncthreads();
        COMPUTE(1)

        float* hdst = hS + ((size_t)(s & 1) * NLAYER + l) * HB + b * HH;
#pragma unroll
        for (int r = 0; r < 3; r++) {
            float gi, gf, gg_, go;
            unpack2(aIF[r], gi, gf);
            unpack2(aGO[r], gg_, go);
            float ig = 1.f / (1.f + expf(-gi));
            float fg = 1.f / (1.f + expf(-gf));
            float G  = tanhf(gg_);
            float og = 1.f / (1.f + expf(-go));
            c_r[r] = fg * c_r[r] + ig * G;
            h_r[r] = og * tanhf(c_r[r]);
            hdst[jg0 + r] = h_r[r];
            if (l == 3) Y3[((size_t)b * LL + t) * HH + jg0 + r] = h_r[r];
        }
    }

    if (writeState) {
#pragma unroll
        for (int r = 0; r < 3; r++) {
            outh[l * HB + b * HH + jg0 + r] = h_r[r];
            outc[l * HB + b * HH + jg0 + r] = c_r[r];
        }
    }
}

// ---------------- causal softmax (exp stored on first pass) ----------------
__global__ __launch_bounds__(256)
void softmax_causal(float* __restrict__ S)
{
    int bq = blockIdx.x;
    int b = bq >> 10, q = bq & 1023;
    float* row = S + ((size_t)b * LL + q) * LL;
    int len = q + 1;
    int tid = threadIdx.x;
    __shared__ float red[256];

    float mx = -1e30f;
    for (int k = tid; k < len; k += 256) mx = fmaxf(mx, row[k]);
    red[tid] = mx; __syncthreads();
    for (int s = 128; s > 0; s >>= 1) {
        if (tid < s) red[tid] = fmaxf(red[tid], red[tid + s]);
        __syncthreads();
    }
    mx = red[0]; __syncthreads();

    float sum = 0.f;
    for (int k = tid; k < len; k += 256) {
        float e = expf(row[k] - mx);
        row[k] = e;                  // store exp; scaled below by same thread
        sum += e;
    }
    red[tid] = sum; __syncthreads();
    for (int s = 128; s > 0; s >>= 1) {
        if (tid < s) red[tid] += red[tid + s];
        __syncthreads();
    }
    sum = red[0]; __syncthreads();

    float inv = 1.f / sum;
    for (int k = tid; k < LL; k += 256)
        row[k] = (k < len) ? row[k] * inv : 0.f;
}

// ---------------- concat [out | ctx] ----------------
__global__ void concat_kernel(const float* __restrict__ Yout, const float* __restrict__ ctx,
                              float* __restrict__ cat)
{
    int i = blockIdx.x * 256 + threadIdx.x;
    if (i >= MM * 2 * HH) return;
    int m = i / (2 * HH), j = i % (2 * HH);
    cat[i] = (j < HH) ? Yout[(size_t)m * HH + j] : ctx[(size_t)m * HH + j - HH];
}

// ---------------- host ----------------
extern "C" void kernel_launch(void* const* d_in, const int* in_sizes, int n_in,
                              void* d_out, int out_size)
{
    const int*   x       = (const int*)d_in[0];
    const float* context = (const float*)d_in[1];
    const float* h_in    = (const float*)d_in[2];
    const float* c_in    = (const float*)d_in[3];
    const float* emb     = (const float*)d_in[4];
    const float* ctx_W   = (const float*)d_in[5];
    const float* ctx_b   = (const float*)d_in[6];
    const float* Wih0    = (const float*)d_in[7];
    const float* WihR    = (const float*)d_in[8];
    const float* Whh     = (const float*)d_in[9];
    const float* bih     = (const float*)d_in[10];
    const float* bhh     = (const float*)d_in[11];
    const float* Wa      = (const float*)d_in[12];
    const float* comb_W  = (const float*)d_in[13];
    const float* comb_b  = (const float*)d_in[14];
    const float* fc_W    = (const float*)d_in[15];
    const float* fc_b    = (const float*)d_in[16];
    float* out = (float*)d_out;

    float *x0, *Y3, *pre, *preT, *keys, *scores, *cat, *comb, *hS;
    unsigned* barCount;
    cudaGetSymbolAddress((void**)&x0,       g_x0);
    cudaGetSymbolAddress((void**)&Y3,       g_seqB);
    cudaGetSymbolAddress((void**)&pre,      g_pre);
    cudaGetSymbolAddress((void**)&preT,     g_preT);
    cudaGetSymbolAddress((void**)&keys,     g_keys);
    cudaGetSymbolAddress((void**)&scores,   g_scores);
    cudaGetSymbolAddress((void**)&cat,      g_cat);
    cudaGetSymbolAddress((void**)&comb,     g_comb);
    cudaGetSymbolAddress((void**)&hS,       g_hS);
    cudaGetSymbolAddress((void**)&barCount, g_barCount);

    const int waveSmem = (2 * 32 * 196 + 4 * 12 * HH * 2) * 4;   // 197,632 B
    cudaFuncSetAttribute(lstm_wave, cudaFuncAttributeMaxDynamicSharedMemorySize, waveSmem);

    const int logitsN = MM * NVOCAB;
    const bool wantState = (out_size >= logitsN + 2 * NLAYER * BB * HH);
    float* outh = out + logitsN;
    float* outc = out + logitsN + NLAYER * BB * HH;

    // 1) embedding + context projection -> x0 [M,256]
    embed_kernel<<<(MM * EMB + 255) / 256, 256>>>(x, emb, x0);
    gemm_tc<<<dim3(1, 256, 1), 256>>>(context, CTXIN, ctx_W, CTXIN, ctx_b, nullptr,
                                      x0 + EMB, 2 * EMB, MM, EMB, CTXIN,
                                      1.f, 0, 0, 0, 1, 0, 0, 0);

    // 2) layer-0 input projection + transpose, then 4-layer wavefront
    gemm_tc<<<dim3(G4 / 128, MM / 128, 1), 256>>>(x0, 2 * EMB, Wih0, 2 * EMB,
                                                  bih, bhh, pre, G4, MM, G4, 2 * EMB,
                                                  1.f, 0, 0, 0, 1, 0, 0, 0);
    transpose_pre<<<dim3(LL, G4 / 32), dim3(32, 32)>>>(pre, preT);
    init_wave_state<<<(NLAYER * HB + 255) / 256, 256>>>(h_in, hS);
    cudaMemsetAsync(barCount, 0, sizeof(unsigned));
    lstm_wave<<<NWCTA, 128, waveSmem>>>(preT, Whh, WihR, bih, bhh, c_in,
                                        Y3, hS, outh, outc, wantState ? 1 : 0);

    // 3) attention
    gemm_tc<<<dim3(HH / 128, MM / 128, 1), 256>>>(Y3, HH, Wa, HH, nullptr, nullptr,
                                                  keys, HH, MM, HH, HH,
                                                  1.f, 0, 0, 0, 1, 0, 0, 0);
    float invs = 1.f / sqrtf((float)HH);
    gemm_tc<<<dim3(8, 8, 32), 256>>>(Y3, HH, keys, HH, nullptr, nullptr,
                                     scores, LL, LL, LL, HH,
                                     invs, 0, 1, 0, 1,
                                     (size_t)LL * HH, (size_t)LL * HH, (size_t)LL * LL);
    softmax_causal<<<BB * LL, 256>>>(scores);
    gemm_tc<<<dim3(HH / 128, 8, 32), 256>>>(scores, LL, Y3, HH, nullptr, nullptr,
                                            keys, HH, LL, HH, LL,
                                            1.f, 0, 0, 1, 0,
                                            (size_t)LL * LL, (size_t)LL * HH, (size_t)LL * HH);

    // 4) combine + output head
    concat_kernel<<<(MM * 2 * HH + 255) / 256, 256>>>(Y3, keys, cat);
    gemm_tc<<<dim3(HH / 128, MM / 128, 1), 256>>>(cat, 2 * HH, comb_W, 2 * HH,
                                                  comb_b, nullptr, comb, HH,
                                                  MM, HH, 2 * HH,
                                                  1.f, 1, 0, 0, 1, 0, 0, 0);
    gemm_tc<<<dim3(1, MM / 128, 1), 256>>>(comb, HH, fc_W, HH, fc_b, nullptr,
                                           out, NVOCAB, MM, NVOCAB, HH,
                                           1.f, 0, 0, 0, 1, 0, 0, 0);
}

// round 13
// speedup vs baseline: 2.7661x; 1.7394x over previous
#include <cuda_runtime.h>
#include <cuda_bf16.h>
#include <math.h>

#define BB 32
#define LL 1024
#define EMB 128
#define HH 384
#define NLAYER 4
#define NVOCAB 100
#define G4 (4*HH)
#define MM (BB*LL)
#define CTXIN 300
#define HB (HH*BB)
#define NWCTA 128          // wavefront CTAs (32 per layer)
#define PA 40              // A smem pitch (b32): conflict-free fragment loads
#define PBW 24             // B smem pitch (b32): conflict-free fragment loads

// ---------------- static scratch ----------------
__device__ float g_x0[MM * 2 * EMB];
__device__ float g_seqB[MM * HH];               // Y3 [B,L,H]
__device__ float g_pre[(size_t)MM * G4];
__device__ float g_preT[(size_t)MM * G4];       // [t][row][b]
__device__ float g_keys[MM * HH];
__device__ float g_scores[(size_t)BB * LL * LL];
__device__ float g_cat[MM * 2 * HH];
__device__ float g_comb[MM * HH];
__device__ float g_hS[2 * NLAYER * HB];         // wavefront state [parity][l][k][b]
__device__ unsigned g_barCount;

// ---------------- barrier helpers ----------------
__device__ __forceinline__ void bar_arrive_release(unsigned* p) {
    asm volatile("red.release.gpu.add.u32 [%0], %1;" :: "l"(p), "r"(1u) : "memory");
}
__device__ __forceinline__ unsigned ld_acquire(unsigned* p) {
    unsigned v;
    asm volatile("ld.acquire.gpu.u32 %0, [%1];" : "=r"(v) : "l"(p) : "memory");
    return v;
}

// ---------------- bf16 split helpers ----------------
__device__ __forceinline__ unsigned pkbf2(float lo_val, float hi_val) {
    unsigned r;
    asm("cvt.rn.bf16x2.f32 %0, %1, %2;" : "=r"(r) : "f"(hi_val), "f"(lo_val));
    return r;
}
__device__ __forceinline__ float bfhi(float x) {
    return __bfloat162float(__float2bfloat16_rn(x));
}
__device__ __forceinline__ void mma16(float* c, const unsigned* a, const unsigned* b) {
    asm volatile(
        "mma.sync.aligned.m16n8k16.row.col.f32.bf16.bf16.f32 "
        "{%0,%1,%2,%3}, {%4,%5,%6,%7}, {%8,%9}, {%0,%1,%2,%3};"
        : "+f"(c[0]), "+f"(c[1]), "+f"(c[2]), "+f"(c[3])
        : "r"(a[0]), "r"(a[1]), "r"(a[2]), "r"(a[3]), "r"(b[0]), "r"(b[1]));
}

// ---------------- tensor-core GEMM (3-pass split-bf16) ----------------
#define SPB 136
__global__ __launch_bounds__(256)
void gemm_tc(const float* __restrict__ A, int lda,
             const float* __restrict__ W, int ldw,
             const float* __restrict__ b1, const float* __restrict__ b2,
             float* __restrict__ C, int ldc,
             int M, int N, int K,
             float scale, int act, int causal, int causalK, int trans,
             size_t sA, size_t sW, size_t sC)
{
    int m0 = blockIdx.y * 128;
    int n0 = blockIdx.x * 128;
    if (causal && n0 > m0 + 127) return;
    A += (size_t)blockIdx.z * sA;
    W += (size_t)blockIdx.z * sW;
    C += (size_t)blockIdx.z * sC;
    int Klim = causalK ? min(K, m0 + 128) : K;

    __shared__ unsigned As_hi[8 * SPB], As_lo[8 * SPB];
    __shared__ unsigned Bs_hi[8 * SPB], Bs_lo[8 * SPB];

    const int tid = threadIdx.x;
    const int lr = tid >> 1, lq = tid & 1;
    const int pB = tid >> 5, nq = (tid & 31) * 4;
    const int lane = tid & 31;
    const int g = lane >> 2, tg = lane & 3;
    const int wid = tid >> 5;
    const int mBase = (wid & 3) * 32;
    const int nBase = (wid >> 2) * 64;

    float acc[2][8][4];
#pragma unroll
    for (int mt = 0; mt < 2; mt++)
#pragma unroll
        for (int nt = 0; nt < 8; nt++)
#pragma unroll
            for (int i = 0; i < 4; i++) acc[mt][nt][i] = 0.f;

    float4 a4[2], b4[2];

#define LOAD_TILE(K0)                                                          \
    {                                                                          \
        int k0_ = (K0);                                                        \
        const float* ap = A + (size_t)(m0 + lr) * lda;                         \
        _Pragma("unroll")                                                      \
        for (int j = 0; j < 2; j++) {                                          \
            int kb = k0_ + lq * 8 + j * 4;                                     \
            float4 v = make_float4(0.f, 0.f, 0.f, 0.f);                        \
            if (kb + 3 < Klim) v = *(const float4*)(ap + kb);                  \
            else {                                                             \
                if (kb + 0 < Klim) v.x = ap[kb + 0];                           \
                if (kb + 1 < Klim) v.y = ap[kb + 1];                           \
                if (kb + 2 < Klim) v.z = ap[kb + 2];                           \
            }                                                                  \
            a4[j] = v;                                                         \
        }                                                                      \
        if (trans) {                                                           \
            int wr = n0 + lr;                                                  \
            const float* wp = W + (size_t)wr * ldw;                            \
            _Pragma("unroll")                                                  \
            for (int j = 0; j < 2; j++) {                                      \
                int kb = k0_ + lq * 8 + j * 4;                                 \
                float4 v = make_float4(0.f, 0.f, 0.f, 0.f);                    \
                if (wr < N) {                                                  \
                    if (kb + 3 < Klim) v = *(const float4*)(wp + kb);          \
                    else {                                                     \
                        if (kb + 0 < Klim) v.x = wp[kb + 0];                   \
                        if (kb + 1 < Klim) v.y = wp[kb + 1];                   \
                        if (kb + 2 < Klim) v.z = wp[kb + 2];                   \
                    }                                                          \
                }                                                              \
                b4[j] = v;                                                     \
            }                                                                  \
        } else {                                                               \
            int kk0 = k0_ + 2 * pB;                                            \
            int kk1 = kk0 + 1;                                                 \
            b4[0] = (kk0 < Klim)                                               \
                  ? *(const float4*)(W + (size_t)kk0 * ldw + n0 + nq)          \
                  : make_float4(0.f, 0.f, 0.f, 0.f);                           \
            b4[1] = (kk1 < Klim)                                               \
                  ? *(const float4*)(W + (size_t)kk1 * ldw + n0 + nq)          \
                  : make_float4(0.f, 0.f, 0.f, 0.f);                           \
        }                                                                      \
    }

    LOAD_TILE(0);

    for (int k0 = 0; k0 < Klim; k0 += 16) {
#pragma unroll
        for (int j = 0; j < 2; j++) {
            float4 e = a4[j];
            int kp = lq * 4 + j * 2;
            float hx = bfhi(e.x), hy = bfhi(e.y), hz = bfhi(e.z), hw = bfhi(e.w);
            As_hi[kp * SPB + lr]       = pkbf2(hx, hy);
            As_hi[(kp + 1) * SPB + lr] = pkbf2(hz, hw);
            As_lo[kp * SPB + lr]       = pkbf2(e.x - hx, e.y - hy);
            As_lo[(kp + 1) * SPB + lr] = pkbf2(e.z - hz, e.w - hw);
        }
        if (trans) {
#pragma unroll
            for (int j = 0; j < 2; j++) {
                float4 e = b4[j];
                int kp = lq * 4 + j * 2;
                float hx = bfhi(e.x), hy = bfhi(e.y), hz = bfhi(e.z), hw = bfhi(e.w);
                Bs_hi[kp * SPB + lr]       = pkbf2(hx, hy);
                Bs_hi[(kp + 1) * SPB + lr] = pkbf2(hz, hw);
                Bs_lo[kp * SPB + lr]       = pkbf2(e.x - hx, e.y - hy);
                Bs_lo[(kp + 1) * SPB + lr] = pkbf2(e.z - hz, e.w - hw);
            }
        } else {
            const float* r0 = &b4[0].x;
            const float* r1 = &b4[1].x;
            unsigned hi4[4], lo4[4];
#pragma unroll
            for (int i = 0; i < 4; i++) {
                float h0 = bfhi(r0[i]), h1 = bfhi(r1[i]);
                hi4[i] = pkbf2(h0, h1);
                lo4[i] = pkbf2(r0[i] - h0, r1[i] - h1);
            }
            *(uint4*)(Bs_hi + pB * SPB + nq) = make_uint4(hi4[0], hi4[1], hi4[2], hi4[3]);
            *(uint4*)(Bs_lo + pB * SPB + nq) = make_uint4(lo4[0], lo4[1], lo4[2], lo4[3]);
        }
        __syncthreads();

        if (k0 + 16 < Klim) LOAD_TILE(k0 + 16);

        unsigned ah[2][4], al[2][4];
#pragma unroll
        for (int mt = 0; mt < 2; mt++) {
            int m = mBase + mt * 16 + g;
            ah[mt][0] = As_hi[tg * SPB + m];
            ah[mt][1] = As_hi[tg * SPB + m + 8];
            ah[mt][2] = As_hi[(tg + 4) * SPB + m];
            ah[mt][3] = As_hi[(tg + 4) * SPB + m + 8];
            al[mt][0] = As_lo[tg * SPB + m];
            al[mt][1] = As_lo[tg * SPB + m + 8];
            al[mt][2] = As_lo[(tg + 4) * SPB + m];
            al[mt][3] = As_lo[(tg + 4) * SPB + m + 8];
        }
#pragma unroll
        for (int nt = 0; nt < 8; nt++) {
            int n = nBase + nt * 8 + g;
            unsigned bh[2], bl[2];
            bh[0] = Bs_hi[tg * SPB + n];
            bh[1] = Bs_hi[(tg + 4) * SPB + n];
            bl[0] = Bs_lo[tg * SPB + n];
            bl[1] = Bs_lo[(tg + 4) * SPB + n];
#pragma unroll
            for (int mt = 0; mt < 2; mt++) {
                mma16(acc[mt][nt], ah[mt], bh);
                mma16(acc[mt][nt], ah[mt], bl);
                mma16(acc[mt][nt], al[mt], bh);
            }
        }
        __syncthreads();
    }

#pragma unroll
    for (int mt = 0; mt < 2; mt++) {
        int row0 = m0 + mBase + mt * 16 + g;
        int row1 = row0 + 8;
#pragma unroll
        for (int nt = 0; nt < 8; nt++) {
            int col = n0 + nBase + nt * 8 + 2 * tg;
            float bias = 0.f, bias1 = 0.f;
            if (col < N) { if (b1) bias += b1[col]; if (b2) bias += b2[col]; }
            if (col + 1 < N) { if (b1) bias1 += b1[col + 1]; if (b2) bias1 += b2[col + 1]; }
            float v0 = acc[mt][nt][0] * scale + bias;
            float v1 = acc[mt][nt][1] * scale + bias1;
            float v2 = acc[mt][nt][2] * scale + bias;
            float v3 = acc[mt][nt][3] * scale + bias1;
            if (act) { v0 = tanhf(v0); v1 = tanhf(v1); v2 = tanhf(v2); v3 = tanhf(v3); }
            if (col + 1 < N) {
                *(float2*)(C + (size_t)row0 * ldc + col) = make_float2(v0, v1);
                *(float2*)(C + (size_t)row1 * ldc + col) = make_float2(v2, v3);
            } else if (col < N) {
                C[(size_t)row0 * ldc + col] = v0;
                C[(size_t)row1 * ldc + col] = v2;
            }
        }
    }
}

// ---------------- embedding gather ----------------
__global__ void embed_kernel(const int* __restrict__ x, const float* __restrict__ emb,
                             float* __restrict__ X0)
{
    int i = blockIdx.x * 256 + threadIdx.x;
    if (i >= MM * EMB) return;
    int m = i >> 7, e = i & 127;
    X0[(size_t)m * 256 + e] = emb[(size_t)x[m] * EMB + e];
}

// ---------------- pre transpose: [b*L+t][row] -> [t][row][b] ------------
__global__ __launch_bounds__(1024)
void transpose_pre(const float* __restrict__ in, float* __restrict__ out)
{
    __shared__ float tile[32][33];
    int t = blockIdx.x;
    int r0 = blockIdx.y * 32;
    int x = threadIdx.x, y = threadIdx.y;
    tile[y][x] = in[((size_t)y * LL + t) * G4 + r0 + x];
    __syncthreads();
    out[((size_t)t * G4 + r0 + y) * BB + x] = tile[x][y];
}

// ---------------- wavefront state init: h_in [l][b][k] -> hS [par][l][k][b] --
__global__ void init_wave_state(const float* __restrict__ h_in, float* __restrict__ hS)
{
    int i = blockIdx.x * 256 + threadIdx.x;
    if (i >= NLAYER * HB) return;
    int l = i / HB, rem = i - l * HB;
    int k = rem >> 5, b = rem & 31;
    hS[(size_t)((l + 1) & 1) * NLAYER * HB + l * HB + k * BB + b] =
        h_in[l * HB + b * HH + k];
}

// ---------------- tensor-core wavefront LSTM: 4 layers, 1027 slots ----------
// 128 CTAs x 128 thr. Per slot per CTA: gates[32,48] = [h;x][32,768] @ Wᵀ via
// 3-pass split-bf16 m16n8k16. Weights resident in smem (converted once).
__global__ __launch_bounds__(128, 1)
void lstm_wave(const float* __restrict__ preT,   // layer0 pre [t][row][b]
               const float* __restrict__ Whh,    // [4][1536][384]
               const float* __restrict__ WihR,   // [3][1536][384]
               const float* __restrict__ bih, const float* __restrict__ bhh,
               const float* __restrict__ c0,     // [4][B][H]
               float* __restrict__ Y3,           // [B][L][H]
               float* __restrict__ hS,           // [2][4][H][B]  (k-major)
               float* __restrict__ outh, float* __restrict__ outc,
               int writeState)
{
    extern __shared__ unsigned smw[];
    unsigned* B0h = smw;                        // [384 kp][24] gate-cols 0-23, hi
    unsigned* B0l = B0h + 384 * PBW;
    unsigned* B1h = B0l + 384 * PBW;            // gate-cols 24-47
    unsigned* B1l = B1h + 384 * PBW;
    unsigned* Ah  = B1l + 384 * PBW;            // [192 kp][40] batch operand, hi
    unsigned* Al  = Ah + 192 * PA;

    const int tid  = threadIdx.x;
    const int wid  = tid >> 5;
    const int lane = tid & 31;
    const int g  = lane >> 2, tg = lane & 3;
    const int l   = blockIdx.x >> 5;
    const int sub = blockIdx.x & 31;
    const int w01 = wid & 1;                    // tile mt parity base

    // ---- convert weights to split-bf16 smem (once) ----
    const float* Whh_l = Whh + (size_t)l * G4 * HH;
    const float* Wih_l = (l > 0) ? (WihR + (size_t)(l - 1) * G4 * HH) : WihR;
    const int kpMax = (l == 0) ? 192 : 384;
    for (int e = tid; e < 48 * 384; e += 128) {
        int kp = e / 48, c = e - kp * 48;
        if (kp < kpMax) {
            int row = sub * 12 + (c >> 2) + (c & 3) * HH;
            float w0, w1;
            if (kp < 192) {
                w0 = Whh_l[(size_t)row * HH + 2 * kp];
                w1 = Whh_l[(size_t)row * HH + 2 * kp + 1];
            } else {
                w0 = Wih_l[(size_t)row * HH + 2 * kp - 384];
                w1 = Wih_l[(size_t)row * HH + 2 * kp - 383];
            }
            float h0 = bfhi(w0), h1 = bfhi(w1);
            unsigned* dh = (c < 24) ? B0h : B1h;
            unsigned* dl = (c < 24) ? B0l : B1l;
            int cc = (c < 24) ? c : c - 24;
            dh[kp * PBW + cc] = pkbf2(h0, h1);
            dl[kp * PBW + cc] = pkbf2(w0 - h0, w1 - h1);
        }
    }

    // ---- per-thread cells (3): tile T = wid*3+i, mt=T&1, nt=T>>1 ----
    int bc[3], jgg[3];
    float c_r[3], h_r[3];
    float bi[3][4];
#pragma unroll
    for (int i = 0; i < 3; i++) {
        int T = wid * 3 + i;
        bc[i]  = 16 * (T & 1) + g + 8 * (tg & 1);
        jgg[i] = sub * 12 + 2 * (T >> 1) + (tg >> 1);
        c_r[i] = c0[l * HB + bc[i] * HH + jgg[i]];
        h_r[i] = 0.f;
#pragma unroll
        for (int q = 0; q < 4; q++)
            bi[i][q] = (l > 0) ? (bih[l * G4 + q * HH + jgg[i]] +
                                  bhh[l * G4 + q * HH + jgg[i]]) : 0.f;
    }

    const int NS = LL + NLAYER - 1;
    for (int s = 0; s < NS; s++) {
        int t = s - l;
        bool active = (t >= 0) && (t < LL);

        float p[12];
        if (active && l == 0) {
#pragma unroll
            for (int i = 0; i < 3; i++)
#pragma unroll
                for (int q = 0; q < 4; q++)
                    p[i * 4 + q] = __ldcg(&preT[((size_t)t * G4 + q * HH + jgg[i]) * BB + bc[i]]);
        }

        // ---- grid barrier ----
        __syncthreads();
        if (tid == 0) {
            bar_arrive_release(&g_barCount);
            unsigned tgt = (unsigned)NWCTA * (unsigned)(s + 1);
            while (ld_acquire(&g_barCount) < tgt) {}
        }
        __syncthreads();
        if (!active) continue;

        const float* hsrc = hS + ((size_t)((s + 1) & 1) * NLAYER + l) * HB;
        const float* xsrc = hS + ((size_t)((s + 1) & 1) * NLAYER + (l - 1)) * HB;

        float acc[3][4];
#pragma unroll
        for (int i = 0; i < 3; i++)
#pragma unroll
            for (int q = 0; q < 4; q++) acc[i][q] = 0.f;

        const int nPhase = (l == 0) ? 1 : 2;
        for (int ph = 0; ph < nPhase; ph++) {
            const float* src = ph ? xsrc : hsrc;

            // stage [384 k][32 b] fp32 -> A [192 kp][PA] bf16x2 hi/lo (coalesced)
#pragma unroll
            for (int it = 0; it < 12; it++) {
                int idx = tid + it * 128;
                int kp = idx >> 3, bq = idx & 7;
                float4 v0 = __ldcv((const float4*)(src + (size_t)(2 * kp) * BB) + bq);
                float4 v1 = __ldcv((const float4*)(src + (size_t)(2 * kp + 1) * BB) + bq);
                float e0 = bfhi(v0.x), e1 = bfhi(v1.x);
                float e2 = bfhi(v0.y), e3 = bfhi(v1.y);
                float e4 = bfhi(v0.z), e5 = bfhi(v1.z);
                float e6 = bfhi(v0.w), e7 = bfhi(v1.w);
                *(uint4*)(Ah + kp * PA + 4 * bq) = make_uint4(
                    pkbf2(e0, e1), pkbf2(e2, e3), pkbf2(e4, e5), pkbf2(e6, e7));
                *(uint4*)(Al + kp * PA + 4 * bq) = make_uint4(
                    pkbf2(v0.x - e0, v1.x - e1), pkbf2(v0.y - e2, v1.y - e3),
                    pkbf2(v0.z - e4, v1.z - e5), pkbf2(v0.w - e6, v1.w - e7));
            }
            __syncthreads();

            int kpB = ph * 192;
            for (int it = 0; it < 24; it++) {
                int r0 = it * 8 + tg;
                int r1 = r0 + 4;
                // A fragments: aF0 for tiles 0,2 (mt=w01), aF1 for tile 1 (mt=w01^1)
                unsigned aF0h[4], aF0l[4], aF1h[4], aF1l[4];
                {
                    int m0_ = w01 * 16 + g;
                    int m1_ = (w01 ^ 1) * 16 + g;
                    aF0h[0] = Ah[r0 * PA + m0_];     aF0h[1] = Ah[r0 * PA + m0_ + 8];
                    aF0h[2] = Ah[r1 * PA + m0_];     aF0h[3] = Ah[r1 * PA + m0_ + 8];
                    aF0l[0] = Al[r0 * PA + m0_];     aF0l[1] = Al[r0 * PA + m0_ + 8];
                    aF0l[2] = Al[r1 * PA + m0_];     aF0l[3] = Al[r1 * PA + m0_ + 8];
                    aF1h[0] = Ah[r0 * PA + m1_];     aF1h[1] = Ah[r0 * PA + m1_ + 8];
                    aF1h[2] = Ah[r1 * PA + m1_];     aF1h[3] = Ah[r1 * PA + m1_ + 8];
                    aF1l[0] = Al[r0 * PA + m1_];     aF1l[1] = Al[r0 * PA + m1_ + 8];
                    aF1l[2] = Al[r1 * PA + m1_];     aF1l[3] = Al[r1 * PA + m1_ + 8];
                }
                // B fragments per tile
                unsigned bh[3][2], bl[3][2];
#pragma unroll
                for (int i = 0; i < 3; i++) {
                    int nt = (wid * 3 + i) >> 1;
                    int cg = nt * 8 + g;
                    const unsigned* BH = (cg < 24) ? B0h : B1h;
                    const unsigned* BL = (cg < 24) ? B0l : B1l;
                    int cc = (cg < 24) ? cg : cg - 24;
                    bh[i][0] = BH[(kpB + r0) * PBW + cc];
                    bh[i][1] = BH[(kpB + r1) * PBW + cc];
                    bl[i][0] = BL[(kpB + r0) * PBW + cc];
                    bl[i][1] = BL[(kpB + r1) * PBW + cc];
                }
                // pass-outer ordering: 3 independent acc chains
                mma16(acc[0], aF0h, bh[0]);
                mma16(acc[1], aF1h, bh[1]);
                mma16(acc[2], aF0h, bh[2]);
                mma16(acc[0], aF0h, bl[0]);
                mma16(acc[1], aF1h, bl[1]);
                mma16(acc[2], aF0h, bl[2]);
                mma16(acc[0], aF0l, bh[0]);
                mma16(acc[1], aF1l, bh[1]);
                mma16(acc[2], aF0l, bh[2]);
            }
            __syncthreads();   // safe A-buffer reuse for next phase
        }

        // ---- combine gates (shfl across tg pairs), activations, state ----
        float* hdst = hS + ((size_t)(s & 1) * NLAYER + l) * HB;
#pragma unroll
        for (int i = 0; i < 3; i++) {
            float x_ = (tg & 1) ? acc[i][0] : acc[i][2];
            float y_ = (tg & 1) ? acc[i][1] : acc[i][3];
            float sx = __shfl_xor_sync(0xffffffffu, x_, 1);
            float sy = __shfl_xor_sync(0xffffffffu, y_, 1);
            float gi, gf, gG, gO;
            if ((tg & 1) == 0) { gi = acc[i][0]; gf = acc[i][1]; gG = sx; gO = sy; }
            else               { gi = sx; gf = sy; gG = acc[i][2]; gO = acc[i][3]; }
            if (l == 0) {
                gi += p[i * 4 + 0]; gf += p[i * 4 + 1];
                gG += p[i * 4 + 2]; gO += p[i * 4 + 3];
            } else {
                gi += bi[i][0]; gf += bi[i][1]; gG += bi[i][2]; gO += bi[i][3];
            }
            float ig = 1.f / (1.f + expf(-gi));
            float fg = 1.f / (1.f + expf(-gf));
            float G  = tanhf(gG);
            float og = 1.f / (1.f + expf(-gO));
            c_r[i] = fg * c_r[i] + ig * G;
            h_r[i] = og * tanhf(c_r[i]);
            hdst[jgg[i] * BB + bc[i]] = h_r[i];
            if (l == 3) Y3[((size_t)bc[i] * LL + t) * HH + jgg[i]] = h_r[i];
        }
    }

    if (writeState) {
#pragma unroll
        for (int i = 0; i < 3; i++) {
            outh[l * HB + bc[i] * HH + jgg[i]] = h_r[i];
            outc[l * HB + bc[i] * HH + jgg[i]] = c_r[i];
        }
    }
}

// ---------------- causal softmax (exp stored on first pass) ----------------
__global__ __launch_bounds__(256)
void softmax_causal(float* __restrict__ S)
{
    int bq = blockIdx.x;
    int b = bq >> 10, q = bq & 1023;
    float* row = S + ((size_t)b * LL + q) * LL;
    int len = q + 1;
    int tid = threadIdx.x;
    __shared__ float red[256];

    float mx = -1e30f;
    for (int k = tid; k < len; k += 256) mx = fmaxf(mx, row[k]);
    red[tid] = mx; __syncthreads();
    for (int s = 128; s > 0; s >>= 1) {
        if (tid < s) red[tid] = fmaxf(red[tid], red[tid + s]);
        __syncthreads();
    }
    mx = red[0]; __syncthreads();

    float sum = 0.f;
    for (int k = tid; k < len; k += 256) {
        float e = expf(row[k] - mx);
        row[k] = e;
        sum += e;
    }
    red[tid] = sum; __syncthreads();
    for (int s = 128; s > 0; s >>= 1) {
        if (tid < s) red[tid] += red[tid + s];
        __syncthreads();
    }
    sum = red[0]; __syncthreads();

    float inv = 1.f / sum;
    for (int k = tid; k < LL; k += 256)
        row[k] = (k < len) ? row[k] * inv : 0.f;
}

// ---------------- concat [out | ctx] ----------------
__global__ void concat_kernel(const float* __restrict__ Yout, const float* __restrict__ ctx,
                              float* __restrict__ cat)
{
    int i = blockIdx.x * 256 + threadIdx.x;
    if (i >= MM * 2 * HH) return;
    int m = i / (2 * HH), j = i % (2 * HH);
    cat[i] = (j < HH) ? Yout[(size_t)m * HH + j] : ctx[(size_t)m * HH + j - HH];
}

// ---------------- host ----------------
extern "C" void kernel_launch(void* const* d_in, const int* in_sizes, int n_in,
                              void* d_out, int out_size)
{
    const int*   x       = (const int*)d_in[0];
    const float* context = (const float*)d_in[1];
    const float* h_in    = (const float*)d_in[2];
    const float* c_in    = (const float*)d_in[3];
    const float* emb     = (const float*)d_in[4];
    const float* ctx_W   = (const float*)d_in[5];
    const float* ctx_b   = (const float*)d_in[6];
    const float* Wih0    = (const float*)d_in[7];
    const float* WihR    = (const float*)d_in[8];
    const float* Whh     = (const float*)d_in[9];
    const float* bih     = (const float*)d_in[10];
    const float* bhh     = (const float*)d_in[11];
    const float* Wa      = (const float*)d_in[12];
    const float* comb_W  = (const float*)d_in[13];
    const float* comb_b  = (const float*)d_in[14];
    const float* fc_W    = (const float*)d_in[15];
    const float* fc_b    = (const float*)d_in[16];
    float* out = (float*)d_out;

    float *x0, *Y3, *pre, *preT, *keys, *scores, *cat, *comb, *hS;
    unsigned* barCount;
    cudaGetSymbolAddress((void**)&x0,       g_x0);
    cudaGetSymbolAddress((void**)&Y3,       g_seqB);
    cudaGetSymbolAddress((void**)&pre,      g_pre);
    cudaGetSymbolAddress((void**)&preT,     g_preT);
    cudaGetSymbolAddress((void**)&keys,     g_keys);
    cudaGetSymbolAddress((void**)&scores,   g_scores);
    cudaGetSymbolAddress((void**)&cat,      g_cat);
    cudaGetSymbolAddress((void**)&comb,     g_comb);
    cudaGetSymbolAddress((void**)&hS,       g_hS);
    cudaGetSymbolAddress((void**)&barCount, g_barCount);

    const int waveSmem = (4 * 384 * PBW + 2 * 192 * PA) * 4;   // 208,896 B
    cudaFuncSetAttribute(lstm_wave, cudaFuncAttributeMaxDynamicSharedMemorySize, waveSmem);

    const int logitsN = MM * NVOCAB;
    const bool wantState = (out_size >= logitsN + 2 * NLAYER * BB * HH);
    float* outh = out + logitsN;
    float* outc = out + logitsN + NLAYER * BB * HH;

    // 1) embedding + context projection -> x0 [M,256]
    embed_kernel<<<(MM * EMB + 255) / 256, 256>>>(x, emb, x0);
    gemm_tc<<<dim3(1, 256, 1), 256>>>(context, CTXIN, ctx_W, CTXIN, ctx_b, nullptr,
                                      x0 + EMB, 2 * EMB, MM, EMB, CTXIN,
                                      1.f, 0, 0, 0, 1, 0, 0, 0);

    // 2) layer-0 input projection + transpose, then 4-layer tensor wavefront
    gemm_tc<<<dim3(G4 / 128, MM / 128, 1), 256>>>(x0, 2 * EMB, Wih0, 2 * EMB,
                                                  bih, bhh, pre, G4, MM, G4, 2 * EMB,
                                                  1.f, 0, 0, 0, 1, 0, 0, 0);
    transpose_pre<<<dim3(LL, G4 / 32), dim3(32, 32)>>>(pre, preT);
    init_wave_state<<<(NLAYER * HB + 255) / 256, 256>>>(h_in, hS);
    cudaMemsetAsync(barCount, 0, sizeof(unsigned));
    lstm_wave<<<NWCTA, 128, waveSmem>>>(preT, Whh, WihR, bih, bhh, c_in,
                                        Y3, hS, outh, outc, wantState ? 1 : 0);

    // 3) attention
    gemm_tc<<<dim3(HH / 128, MM / 128, 1), 256>>>(Y3, HH, Wa, HH, nullptr, nullptr,
                                                  keys, HH, MM, HH, HH,
                                                  1.f, 0, 0, 0, 1, 0, 0, 0);
    float invs = 1.f / sqrtf((float)HH);
    gemm_tc<<<dim3(8, 8, 32), 256>>>(Y3, HH, keys, HH, nullptr, nullptr,
                                     scores, LL, LL, LL, HH,
                                     invs, 0, 1, 0, 1,
                                     (size_t)LL * HH, (size_t)LL * HH, (size_t)LL * LL);
    softmax_causal<<<BB * LL, 256>>>(scores);
    gemm_tc<<<dim3(HH / 128, 8, 32), 256>>>(scores, LL, Y3, HH, nullptr, nullptr,
                                            keys, HH, LL, HH, LL,
                                            1.f, 0, 0, 1, 0,
                                            (size_t)LL * LL, (size_t)LL * HH, (size_t)LL * HH);

    // 4) combine + output head
    concat_kernel<<<(MM * 2 * HH + 255) / 256, 256>>>(Y3, keys, cat);
    gemm_tc<<<dim3(HH / 128, MM / 128, 1), 256>>>(cat, 2 * HH, comb_W, 2 * HH,
                                                  comb_b, nullptr, comb, HH,
                                                  MM, HH, 2 * HH,
                                                  1.f, 1, 0, 0, 1, 0, 0, 0);
    gemm_tc<<<dim3(1, MM / 128, 1), 256>>>(comb, HH, fc_W, HH, fc_b, nullptr,
                                           out, NVOCAB, MM, NVOCAB, HH,
                                           1.f, 0, 0, 0, 1, 0, 0, 0);
}

// round 15
// speedup vs baseline: 3.0728x; 1.1109x over previous
#include <cuda_runtime.h>
#include <cuda_bf16.h>
#include <math.h>

#define BB 32
#define LL 1024
#define EMB 128
#define HH 384
#define NLAYER 4
#define NVOCAB 100
#define G4 (4*HH)
#define MM (BB*LL)
#define CTXIN 300
#define HB (HH*BB)
#define NWCTA 128          // wavefront CTAs (32 per layer)
#define P2A 36             // A smem pitch (uint2): 36%16==4 -> conflict-free LDS.64
#define P2B 52             // B smem pitch (uint2): 52%16==4 -> conflict-free LDS.64

// ---------------- static scratch ----------------
__device__ float g_x0[MM * 2 * EMB];
__device__ float g_seqB[MM * HH];               // Y3 [B,L,H]
__device__ float g_pre[(size_t)MM * G4];
__device__ float g_preT[(size_t)MM * G4];       // [t][row][b]
__device__ float g_keys[MM * HH];
__device__ float g_scores[(size_t)BB * LL * LL];
__device__ float g_cat[MM * 2 * HH];
__device__ float g_comb[MM * HH];
__device__ uint2 g_hSp[2 * NLAYER * 192 * BB];  // packed split-bf16 state [par][l][kp][b]
__device__ unsigned g_barCount;

// ---------------- barrier helpers ----------------
__device__ __forceinline__ void bar_arrive_release(unsigned* p) {
    asm volatile("red.release.gpu.add.u32 [%0], %1;" :: "l"(p), "r"(1u) : "memory");
}
__device__ __forceinline__ unsigned ld_acquire(unsigned* p) {
    unsigned v;
    asm volatile("ld.acquire.gpu.u32 %0, [%1];" : "=r"(v) : "l"(p) : "memory");
    return v;
}

// ---------------- bf16 split helpers ----------------
__device__ __forceinline__ unsigned pkbf2(float lo_val, float hi_val) {
    unsigned r;
    asm("cvt.rn.bf16x2.f32 %0, %1, %2;" : "=r"(r) : "f"(hi_val), "f"(lo_val));
    return r;
}
__device__ __forceinline__ float bfhi(float x) {
    return __bfloat162float(__float2bfloat16_rn(x));
}
__device__ __forceinline__ void mma16(float* c, const unsigned* a, const unsigned* b) {
    asm volatile(
        "mma.sync.aligned.m16n8k16.row.col.f32.bf16.bf16.f32 "
        "{%0,%1,%2,%3}, {%4,%5,%6,%7}, {%8,%9}, {%0,%1,%2,%3};"
        : "+f"(c[0]), "+f"(c[1]), "+f"(c[2]), "+f"(c[3])
        : "r"(a[0]), "r"(a[1]), "r"(a[2]), "r"(a[3]), "r"(b[0]), "r"(b[1]));
}

// ---------------- tensor-core GEMM (3-pass split-bf16) ----------------
#define SPB 136
__global__ __launch_bounds__(256)
void gemm_tc(const float* __restrict__ A, int lda,
             const float* __restrict__ W, int ldw,
             const float* __restrict__ b1, const float* __restrict__ b2,
             float* __restrict__ C, int ldc,
             int M, int N, int K,
             float scale, int act, int causal, int causalK, int trans,
             size_t sA, size_t sW, size_t sC)
{
    int m0 = blockIdx.y * 128;
    int n0 = blockIdx.x * 128;
    if (causal && n0 > m0 + 127) return;
    A += (size_t)blockIdx.z * sA;
    W += (size_t)blockIdx.z * sW;
    C += (size_t)blockIdx.z * sC;
    int Klim = causalK ? min(K, m0 + 128) : K;

    __shared__ unsigned As_hi[8 * SPB], As_lo[8 * SPB];
    __shared__ unsigned Bs_hi[8 * SPB], Bs_lo[8 * SPB];

    const int tid = threadIdx.x;
    const int lr = tid >> 1, lq = tid & 1;
    const int pB = tid >> 5, nq = (tid & 31) * 4;
    const int lane = tid & 31;
    const int g = lane >> 2, tg = lane & 3;
    const int wid = tid >> 5;
    const int mBase = (wid & 3) * 32;
    const int nBase = (wid >> 2) * 64;

    float acc[2][8][4];
#pragma unroll
    for (int mt = 0; mt < 2; mt++)
#pragma unroll
        for (int nt = 0; nt < 8; nt++)
#pragma unroll
            for (int i = 0; i < 4; i++) acc[mt][nt][i] = 0.f;

    float4 a4[2], b4[2];

#define LOAD_TILE(K0)                                                          \
    {                                                                          \
        int k0_ = (K0);                                                        \
        const float* ap = A + (size_t)(m0 + lr) * lda;                         \
        _Pragma("unroll")                                                      \
        for (int j = 0; j < 2; j++) {                                          \
            int kb = k0_ + lq * 8 + j * 4;                                     \
            float4 v = make_float4(0.f, 0.f, 0.f, 0.f);                        \
            if (kb + 3 < Klim) v = *(const float4*)(ap + kb);                  \
            else {                                                             \
                if (kb + 0 < Klim) v.x = ap[kb + 0];                           \
                if (kb + 1 < Klim) v.y = ap[kb + 1];                           \
                if (kb + 2 < Klim) v.z = ap[kb + 2];                           \
            }                                                                  \
            a4[j] = v;                                                         \
        }                                                                      \
        if (trans) {                                                           \
            int wr = n0 + lr;                                                  \
            const float* wp = W + (size_t)wr * ldw;                            \
            _Pragma("unroll")                                                  \
            for (int j = 0; j < 2; j++) {                                      \
                int kb = k0_ + lq * 8 + j * 4;                                 \
                float4 v = make_float4(0.f, 0.f, 0.f, 0.f);                    \
                if (wr < N) {                                                  \
                    if (kb + 3 < Klim) v = *(const float4*)(wp + kb);          \
                    else {                                                     \
                        if (kb + 0 < Klim) v.x = wp[kb + 0];                   \
                        if (kb + 1 < Klim) v.y = wp[kb + 1];                   \
                        if (kb + 2 < Klim) v.z = wp[kb + 2];                   \
                    }                                                          \
                }                                                              \
                b4[j] = v;                                                     \
            }                                                                  \
        } else {                                                               \
            int kk0 = k0_ + 2 * pB;                                            \
            int kk1 = kk0 + 1;                                                 \
            b4[0] = (kk0 < Klim)                                               \
                  ? *(const float4*)(W + (size_t)kk0 * ldw + n0 + nq)          \
                  : make_float4(0.f, 0.f, 0.f, 0.f);                           \
            b4[1] = (kk1 < Klim)                                               \
                  ? *(const float4*)(W + (size_t)kk1 * ldw + n0 + nq)          \
                  : make_float4(0.f, 0.f, 0.f, 0.f);                           \
        }                                                                      \
    }

    LOAD_TILE(0);

    for (int k0 = 0; k0 < Klim; k0 += 16) {
#pragma unroll
        for (int j = 0; j < 2; j++) {
            float4 e = a4[j];
            int kp = lq * 4 + j * 2;
            float hx = bfhi(e.x), hy = bfhi(e.y), hz = bfhi(e.z), hw = bfhi(e.w);
            As_hi[kp * SPB + lr]       = pkbf2(hx, hy);
            As_hi[(kp + 1) * SPB + lr] = pkbf2(hz, hw);
            As_lo[kp * SPB + lr]       = pkbf2(e.x - hx, e.y - hy);
            As_lo[(kp + 1) * SPB + lr] = pkbf2(e.z - hz, e.w - hw);
        }
        if (trans) {
#pragma unroll
            for (int j = 0; j < 2; j++) {
                float4 e = b4[j];
                int kp = lq * 4 + j * 2;
                float hx = bfhi(e.x), hy = bfhi(e.y), hz = bfhi(e.z), hw = bfhi(e.w);
                Bs_hi[kp * SPB + lr]       = pkbf2(hx, hy);
                Bs_hi[(kp + 1) * SPB + lr] = pkbf2(hz, hw);
                Bs_lo[kp * SPB + lr]       = pkbf2(e.x - hx, e.y - hy);
                Bs_lo[(kp + 1) * SPB + lr] = pkbf2(e.z - hz, e.w - hw);
            }
        } else {
            const float* r0 = &b4[0].x;
            const float* r1 = &b4[1].x;
            unsigned hi4[4], lo4[4];
#pragma unroll
            for (int i = 0; i < 4; i++) {
                float h0 = bfhi(r0[i]), h1 = bfhi(r1[i]);
                hi4[i] = pkbf2(h0, h1);
                lo4[i] = pkbf2(r0[i] - h0, r1[i] - h1);
            }
            *(uint4*)(Bs_hi + pB * SPB + nq) = make_uint4(hi4[0], hi4[1], hi4[2], hi4[3]);
            *(uint4*)(Bs_lo + pB * SPB + nq) = make_uint4(lo4[0], lo4[1], lo4[2], lo4[3]);
        }
        __syncthreads();

        if (k0 + 16 < Klim) LOAD_TILE(k0 + 16);

        unsigned ah[2][4], al[2][4];
#pragma unroll
        for (int mt = 0; mt < 2; mt++) {
            int m = mBase + mt * 16 + g;
            ah[mt][0] = As_hi[tg * SPB + m];
            ah[mt][1] = As_hi[tg * SPB + m + 8];
            ah[mt][2] = As_hi[(tg + 4) * SPB + m];
            ah[mt][3] = As_hi[(tg + 4) * SPB + m + 8];
            al[mt][0] = As_lo[tg * SPB + m];
            al[mt][1] = As_lo[tg * SPB + m + 8];
            al[mt][2] = As_lo[(tg + 4) * SPB + m];
            al[mt][3] = As_lo[(tg + 4) * SPB + m + 8];
        }
#pragma unroll
        for (int nt = 0; nt < 8; nt++) {
            int n = nBase + nt * 8 + g;
            unsigned bh[2], bl[2];
            bh[0] = Bs_hi[tg * SPB + n];
            bh[1] = Bs_hi[(tg + 4) * SPB + n];
            bl[0] = Bs_lo[tg * SPB + n];
            bl[1] = Bs_lo[(tg + 4) * SPB + n];
#pragma unroll
            for (int mt = 0; mt < 2; mt++) {
                mma16(acc[mt][nt], ah[mt], bh);
                mma16(acc[mt][nt], ah[mt], bl);
                mma16(acc[mt][nt], al[mt], bh);
            }
        }
        __syncthreads();
    }

#pragma unroll
    for (int mt = 0; mt < 2; mt++) {
        int row0 = m0 + mBase + mt * 16 + g;
        int row1 = row0 + 8;
#pragma unroll
        for (int nt = 0; nt < 8; nt++) {
            int col = n0 + nBase + nt * 8 + 2 * tg;
            float bias = 0.f, bias1 = 0.f;
            if (col < N) { if (b1) bias += b1[col]; if (b2) bias += b2[col]; }
            if (col + 1 < N) { if (b1) bias1 += b1[col + 1]; if (b2) bias1 += b2[col + 1]; }
            float v0 = acc[mt][nt][0] * scale + bias;
            float v1 = acc[mt][nt][1] * scale + bias1;
            float v2 = acc[mt][nt][2] * scale + bias;
            float v3 = acc[mt][nt][3] * scale + bias1;
            if (act) { v0 = tanhf(v0); v1 = tanhf(v1); v2 = tanhf(v2); v3 = tanhf(v3); }
            if (col + 1 < N) {
                *(float2*)(C + (size_t)row0 * ldc + col) = make_float2(v0, v1);
                *(float2*)(C + (size_t)row1 * ldc + col) = make_float2(v2, v3);
            } else if (col < N) {
                C[(size_t)row0 * ldc + col] = v0;
                C[(size_t)row1 * ldc + col] = v2;
            }
        }
    }
}

// ---------------- embedding gather ----------------
__global__ void embed_kernel(const int* __restrict__ x, const float* __restrict__ emb,
                             float* __restrict__ X0)
{
    int i = blockIdx.x * 256 + threadIdx.x;
    if (i >= MM * EMB) return;
    int m = i >> 7, e = i & 127;
    X0[(size_t)m * 256 + e] = emb[(size_t)x[m] * EMB + e];
}

// ---------------- pre transpose: [b*L+t][row] -> [t][row][b] ------------
__global__ __launch_bounds__(1024)
void transpose_pre(const float* __restrict__ in, float* __restrict__ out)
{
    __shared__ float tile[32][33];
    int t = blockIdx.x;
    int r0 = blockIdx.y * 32;
    int x = threadIdx.x, y = threadIdx.y;
    tile[y][x] = in[((size_t)y * LL + t) * G4 + r0 + x];
    __syncthreads();
    out[((size_t)t * G4 + r0 + y) * BB + x] = tile[x][y];
}

// ---------------- wavefront state init: h_in [l][b][k] -> packed hSp -------
__global__ void init_wave_state(const float* __restrict__ h_in, uint2* __restrict__ hSp)
{
    int i = blockIdx.x * 256 + threadIdx.x;
    if (i >= NLAYER * 192 * BB) return;
    int l = i / (192 * BB), rem = i - l * (192 * BB);
    int kp = rem >> 5, b = rem & 31;
    float h0 = h_in[l * HB + b * HH + 2 * kp];
    float h1 = h_in[l * HB + b * HH + 2 * kp + 1];
    float e0 = bfhi(h0), e1 = bfhi(h1);
    hSp[((size_t)((l + 1) & 1) * NLAYER + l) * (192 * BB) + kp * BB + b] =
        make_uint2(pkbf2(e0, e1), pkbf2(h0 - e0, h1 - e1));
}

// ---------------- tensor-core wavefront LSTM: 4 layers, 1027 slots ----------
// 128 CTAs x 128 thr. State packed split-bf16 in global (producer-side pack);
// smem: weights uint2[384][52], A stage uint2[192][36]. Warp owns one mt.
__global__ __launch_bounds__(128, 1)
void lstm_wave(const float* __restrict__ preT,   // layer0 pre [t][row][b]
               const float* __restrict__ Whh,    // [4][1536][384]
               const float* __restrict__ WihR,   // [3][1536][384]
               const float* __restrict__ bih, const float* __restrict__ bhh,
               const float* __restrict__ c0,     // [4][B][H]
               float* __restrict__ Y3,           // [B][L][H]
               uint2* __restrict__ hSp,          // [2][4][192][32] packed
               float* __restrict__ outh, float* __restrict__ outc,
               int writeState)
{
    extern __shared__ uint2 sm2[];
    uint2* Bw  = sm2;                   // [384 kp][P2B]
    uint2* Asm = sm2 + 384 * P2B;       // [192 kp][P2A]

    const int tid  = threadIdx.x;
    const int wid  = tid >> 5;
    const int lane = tid & 31;
    const int g  = lane >> 2, tg = lane & 3;
    const int l   = blockIdx.x >> 5;
    const int sub = blockIdx.x & 31;
    const int mt16   = (wid & 1) * 16;
    const int ntBase = (wid >> 1) * 3;

    // ---- convert weights to packed split-bf16 smem (once) ----
    const float* Whh_l = Whh + (size_t)l * G4 * HH;
    const float* Wih_l = (l > 0) ? (WihR + (size_t)(l - 1) * G4 * HH) : WihR;
    const int kpMax = (l == 0) ? 192 : 384;
    for (int e = tid; e < 48 * 384; e += 128) {
        int kp = e / 48, c = e - kp * 48;
        if (kp < kpMax) {
            int row = sub * 12 + (c >> 2) + (c & 3) * HH;
            float w0, w1;
            if (kp < 192) {
                w0 = Whh_l[(size_t)row * HH + 2 * kp];
                w1 = Whh_l[(size_t)row * HH + 2 * kp + 1];
            } else {
                w0 = Wih_l[(size_t)row * HH + 2 * kp - 384];
                w1 = Wih_l[(size_t)row * HH + 2 * kp - 383];
            }
            float h0 = bfhi(w0), h1 = bfhi(w1);
            Bw[kp * P2B + c] = make_uint2(pkbf2(h0, h1), pkbf2(w0 - h0, w1 - h1));
        }
    }

    // ---- per-thread cells (3): warp-fixed mt, nt = ntBase + i ----
    int bc[3], jgg[3];
    float c_r[3], h_r[3];
    float bi[3][4];
#pragma unroll
    for (int i = 0; i < 3; i++) {
        bc[i]  = mt16 + g + 8 * (tg & 1);
        jgg[i] = sub * 12 + 2 * (ntBase + i) + (tg >> 1);
        c_r[i] = c0[l * HB + bc[i] * HH + jgg[i]];
        h_r[i] = 0.f;
#pragma unroll
        for (int q = 0; q < 4; q++)
            bi[i][q] = (l > 0) ? (bih[l * G4 + q * HH + jgg[i]] +
                                  bhh[l * G4 + q * HH + jgg[i]]) : 0.f;
    }

    const int NS = LL + NLAYER - 1;
    for (int s = 0; s < NS; s++) {
        int t = s - l;
        bool active = (t >= 0) && (t < LL);

        float p[12];
        if (active && l == 0) {
#pragma unroll
            for (int i = 0; i < 3; i++)
#pragma unroll
                for (int q = 0; q < 4; q++)
                    p[i * 4 + q] = __ldcg(&preT[((size_t)t * G4 + q * HH + jgg[i]) * BB + bc[i]]);
        }

        // ---- grid barrier ----
        __syncthreads();
        if (tid == 0) {
            bar_arrive_release(&g_barCount);
            unsigned tgt = (unsigned)NWCTA * (unsigned)(s + 1);
            while (ld_acquire(&g_barCount) < tgt) {}
        }
        __syncthreads();
        if (!active) continue;

        const uint2* hsrcP = hSp + ((size_t)((s + 1) & 1) * NLAYER + l) * (192 * BB);
        const uint2* xsrcP = hSp + ((size_t)((s + 1) & 1) * NLAYER + (l - 1)) * (192 * BB);

        float acc[3][4];
#pragma unroll
        for (int i = 0; i < 3; i++)
#pragma unroll
            for (int q = 0; q < 4; q++) acc[i][q] = 0.f;

        const int nPhase = (l == 0) ? 1 : 2;
        for (int ph = 0; ph < nPhase; ph++) {
            // ---- stage packed A: pure copy, no conversion ----
            const uint4* src4 = (const uint4*)(ph ? xsrcP : hsrcP);
#pragma unroll
            for (int it = 0; it < 24; it++) {
                int idx = tid + it * 128;          // uint4 index, 0..3071
                int kp = idx >> 4, bp = idx & 15;  // uint4 covers b = 2bp, 2bp+1
                uint4 v = __ldcv(src4 + idx);
                *(uint4*)(Asm + kp * P2A + 2 * bp) = v;
            }
            __syncthreads();

            int kpB = ph * 192;
            for (int it = 0; it < 24; it++) {
                int r0 = it * 8 + tg, r1 = r0 + 4;
                const uint2* Ar0 = Asm + r0 * P2A + mt16 + g;
                const uint2* Ar1 = Asm + r1 * P2A + mt16 + g;
                uint2 a0 = Ar0[0], a1 = Ar0[8], a2 = Ar1[0], a3 = Ar1[8];
                unsigned ah[4] = {a0.x, a1.x, a2.x, a3.x};
                unsigned al[4] = {a0.y, a1.y, a2.y, a3.y};
                const uint2* Br0 = Bw + (kpB + r0) * P2B + g;
                const uint2* Br1 = Bw + (kpB + r1) * P2B + g;
#pragma unroll
                for (int i = 0; i < 3; i++) {
                    int co = (ntBase + i) * 8;
                    uint2 b0 = Br0[co], b1 = Br1[co];
                    unsigned bh[2] = {b0.x, b1.x};
                    unsigned bl[2] = {b0.y, b1.y};
                    mma16(acc[i], ah, bh);
                    mma16(acc[i], ah, bl);
                    mma16(acc[i], al, bh);
                }
            }
            if (ph + 1 < nPhase) __syncthreads();   // A-buffer reuse
        }

        // ---- combine gates, activations, pack + write state ----
        uint2* hdst = hSp + ((size_t)(s & 1) * NLAYER + l) * (192 * BB);
#pragma unroll
        for (int i = 0; i < 3; i++) {
            float x_ = (tg & 1) ? acc[i][0] : acc[i][2];
            float y_ = (tg & 1) ? acc[i][1] : acc[i][3];
            float sx = __shfl_xor_sync(0xffffffffu, x_, 1);
            float sy = __shfl_xor_sync(0xffffffffu, y_, 1);
            float gi, gf, gG, gO;
            if ((tg & 1) == 0) { gi = acc[i][0]; gf = acc[i][1]; gG = sx; gO = sy; }
            else               { gi = sx; gf = sy; gG = acc[i][2]; gO = acc[i][3]; }
            if (l == 0) {
                gi += p[i * 4 + 0]; gf += p[i * 4 + 1];
                gG += p[i * 4 + 2]; gO += p[i * 4 + 3];
            } else {
                gi += bi[i][0]; gf += bi[i][1]; gG += bi[i][2]; gO += bi[i][3];
            }
            float ig = 1.f / (1.f + expf(-gi));
            float fg = 1.f / (1.f + expf(-gf));
            float G  = tanhf(gG);
            float og = 1.f / (1.f + expf(-gO));
            c_r[i] = fg * c_r[i] + ig * G;
            h_r[i] = og * tanhf(c_r[i]);

            // pack (jg even, jg odd) on same b via shfl, even lane stores
            float hpart = __shfl_xor_sync(0xffffffffu, h_r[i], 2);
            if ((tg & 2) == 0) {
                float he = h_r[i];
                float ee = bfhi(he), eo = bfhi(hpart);
                hdst[(jgg[i] >> 1) * BB + bc[i]] =
                    make_uint2(pkbf2(ee, eo), pkbf2(he - ee, hpart - eo));
            }
            if (l == 3) Y3[((size_t)bc[i] * LL + t) * HH + jgg[i]] = h_r[i];
        }
    }

    if (writeState) {
#pragma unroll
        for (int i = 0; i < 3; i++) {
            outh[l * HB + bc[i] * HH + jgg[i]] = h_r[i];
            outc[l * HB + bc[i] * HH + jgg[i]] = c_r[i];
        }
    }
}

// ---------------- causal softmax (exp stored on first pass) ----------------
__global__ __launch_bounds__(256)
void softmax_causal(float* __restrict__ S)
{
    int bq = blockIdx.x;
    int b = bq >> 10, q = bq & 1023;
    float* row = S + ((size_t)b * LL + q) * LL;
    int len = q + 1;
    int tid = threadIdx.x;
    __shared__ float red[256];

    float mx = -1e30f;
    for (int k = tid; k < len; k += 256) mx = fmaxf(mx, row[k]);
    red[tid] = mx; __syncthreads();
    for (int s = 128; s > 0; s >>= 1) {
        if (tid < s) red[tid] = fmaxf(red[tid], red[tid + s]);
        __syncthreads();
    }
    mx = red[0]; __syncthreads();

    float sum = 0.f;
    for (int k = tid; k < len; k += 256) {
        float e = expf(row[k] - mx);
        row[k] = e;
        sum += e;
    }
    red[tid] = sum; __syncthreads();
    for (int s = 128; s > 0; s >>= 1) {
        if (tid < s) red[tid] += red[tid + s];
        __syncthreads();
    }
    sum = red[0]; __syncthreads();

    float inv = 1.f / sum;
    for (int k = tid; k < LL; k += 256)
        row[k] = (k < len) ? row[k] * inv : 0.f;
}

// ---------------- concat [out | ctx] ----------------
__global__ void concat_kernel(const float* __restrict__ Yout, const float* __restrict__ ctx,
                              float* __restrict__ cat)
{
    int i = blockIdx.x * 256 + threadIdx.x;
    if (i >= MM * 2 * HH) return;
    int m = i / (2 * HH), j = i % (2 * HH);
    cat[i] = (j < HH) ? Yout[(size_t)m * HH + j] : ctx[(size_t)m * HH + j - HH];
}

// ---------------- host ----------------
extern "C" void kernel_launch(void* const* d_in, const int* in_sizes, int n_in,
                              void* d_out, int out_size)
{
    const int*   x       = (const int*)d_in[0];
    const float* context = (const float*)d_in[1];
    const float* h_in    = (const float*)d_in[2];
    const float* c_in    = (const float*)d_in[3];
    const float* emb     = (const float*)d_in[4];
    const float* ctx_W   = (const float*)d_in[5];
    const float* ctx_b   = (const float*)d_in[6];
    const float* Wih0    = (const float*)d_in[7];
    const float* WihR    = (const float*)d_in[8];
    const float* Whh     = (const float*)d_in[9];
    const float* bih     = (const float*)d_in[10];
    const float* bhh     = (const float*)d_in[11];
    const float* Wa      = (const float*)d_in[12];
    const float* comb_W  = (const float*)d_in[13];
    const float* comb_b  = (const float*)d_in[14];
    const float* fc_W    = (const float*)d_in[15];
    const float* fc_b    = (const float*)d_in[16];
    float* out = (float*)d_out;

    float *x0, *Y3, *pre, *preT, *keys, *scores, *cat, *comb;
    uint2* hSp;
    unsigned* barCount;
    cudaGetSymbolAddress((void**)&x0,       g_x0);
    cudaGetSymbolAddress((void**)&Y3,       g_seqB);
    cudaGetSymbolAddress((void**)&pre,      g_pre);
    cudaGetSymbolAddress((void**)&preT,     g_preT);
    cudaGetSymbolAddress((void**)&keys,     g_keys);
    cudaGetSymbolAddress((void**)&scores,   g_scores);
    cudaGetSymbolAddress((void**)&cat,      g_cat);
    cudaGetSymbolAddress((void**)&comb,     g_comb);
    cudaGetSymbolAddress((void**)&hSp,      g_hSp);
    cudaGetSymbolAddress((void**)&barCount, g_barCount);

    const int waveSmem = (384 * P2B + 192 * P2A) * 8;   // 215,040 B
    cudaFuncSetAttribute(lstm_wave, cudaFuncAttributeMaxDynamicSharedMemorySize, waveSmem);

    const int logitsN = MM * NVOCAB;
    const bool wantState = (out_size >= logitsN + 2 * NLAYER * BB * HH);
    float* outh = out + logitsN;
    float* outc = out + logitsN + NLAYER * BB * HH;

    // 1) embedding + context projection -> x0 [M,256]
    embed_kernel<<<(MM * EMB + 255) / 256, 256>>>(x, emb, x0);
    gemm_tc<<<dim3(1, 256, 1), 256>>>(context, CTXIN, ctx_W, CTXIN, ctx_b, nullptr,
                                      x0 + EMB, 2 * EMB, MM, EMB, CTXIN,
                                      1.f, 0, 0, 0, 1, 0, 0, 0);

    // 2) layer-0 input projection + transpose, then 4-layer tensor wavefront
    gemm_tc<<<dim3(G4 / 128, MM / 128, 1), 256>>>(x0, 2 * EMB, Wih0, 2 * EMB,
                                                  bih, bhh, pre, G4, MM, G4, 2 * EMB,
                                                  1.f, 0, 0, 0, 1, 0, 0, 0);
    transpose_pre<<<dim3(LL, G4 / 32), dim3(32, 32)>>>(pre, preT);
    init_wave_state<<<(NLAYER * 192 * BB + 255) / 256, 256>>>(h_in, hSp);
    cudaMemsetAsync(barCount, 0, sizeof(unsigned));
    lstm_wave<<<NWCTA, 128, waveSmem>>>(preT, Whh, WihR, bih, bhh, c_in,
                                        Y3, hSp, outh, outc, wantState ? 1 : 0);

    // 3) attention
    gemm_tc<<<dim3(HH / 128, MM / 128, 1), 256>>>(Y3, HH, Wa, HH, nullptr, nullptr,
                                                  keys, HH, MM, HH, HH,
                                                  1.f, 0, 0, 0, 1, 0, 0, 0);
    float invs = 1.f / sqrtf((float)HH);
    gemm_tc<<<dim3(8, 8, 32), 256>>>(Y3, HH, keys, HH, nullptr, nullptr,
                                     scores, LL, LL, LL, HH,
                                     invs, 0, 1, 0, 1,
                                     (size_t)LL * HH, (size_t)LL * HH, (size_t)LL * LL);
    softmax_causal<<<BB * LL, 256>>>(scores);
    gemm_tc<<<dim3(HH / 128, 8, 32), 256>>>(scores, LL, Y3, HH, nullptr, nullptr,
                                            keys, HH, LL, HH, LL,
                                            1.f, 0, 0, 1, 0,
                                            (size_t)LL * LL, (size_t)LL * HH, (size_t)LL * HH);

    // 4) combine + output head
    concat_kernel<<<(MM * 2 * HH + 255) / 256, 256>>>(Y3, keys, cat);
    gemm_tc<<<dim3(HH / 128, MM / 128, 1), 256>>>(cat, 2 * HH, comb_W, 2 * HH,
                                                  comb_b, nullptr, comb, HH,
                                                  MM, HH, 2 * HH,
                                                  1.f, 1, 0, 0, 1, 0, 0, 0);
    gemm_tc<<<dim3(1, MM / 128, 1), 256>>>(comb, HH, fc_W, HH, fc_b, nullptr,
                                           out, NVOCAB, MM, NVOCAB, HH,
                                           1.f, 0, 0, 0, 1, 0, 0, 0);
}